// round 6
// baseline (speedup 1.0000x reference)
#include <cuda_runtime.h>
#include <cstdint>
#include <math.h>

#define BB   128      // batch
#define TT   256      // timesteps
#define HH   512      // hidden
#define EE   300      // embed dim
#define GG   2048     // 4H
#define HB   (HH*BB)  // one h buffer (transposed [k][b]) = 65536 floats

// ---------------- device scratch (static, no allocation) ----------------
__device__ float g_xproj[(size_t)TT * GG * BB];   // [t][col][b]  256MB
__device__ float g_Wp0t[(size_t)GG * HH];         // [c][k4:128][cp:8][2cols x 4k]
__device__ float g_Wp1t[(size_t)GG * 2 * HH];     // [c][k4:256][cp:8][2cols x 4k]
__device__ float g_h0t[2 * HB];                   // transposed [k][b], ping-pong
__device__ float g_h1t[2 * HB];
__device__ unsigned g_bar_count;
__device__ unsigned g_bar_gen;
__device__ int g_odd_nonzero;                     // 1 -> x buffer is int32 layout

// ---------------- helpers ----------------
typedef unsigned long long ull;

__device__ __forceinline__ ull bcast2(float v) {
    ull r; asm("mov.b64 %0, {%1, %1};" : "=l"(r) : "f"(v)); return r;
}
__device__ __forceinline__ ull fma2(ull a, ull b, ull c) {
    ull d; asm("fma.rn.f32x2 %0, %1, %2, %3;" : "=l"(d) : "l"(a), "l"(b), "l"(c)); return d;
}
__device__ __forceinline__ float sigf(float x) { return 1.0f / (1.0f + expf(-x)); }

__device__ __forceinline__ void grid_barrier() {
    __syncthreads();
    if (threadIdx.x == 0) {
        __threadfence();
        unsigned gen = *((volatile unsigned*)&g_bar_gen);
        unsigned ticket = atomicAdd(&g_bar_count, 1u);
        if (ticket == gridDim.x - 1) {
            atomicExch(&g_bar_count, 0u);
            __threadfence();
            atomicAdd(&g_bar_gen, 1u);
        } else {
            while (*((volatile unsigned*)&g_bar_gen) == gen) {}
            __threadfence();
        }
    }
    __syncthreads();
}

__device__ __forceinline__ void cp16(uint32_t saddr, const float* g) {
    asm volatile("cp.async.cg.shared.global [%0], [%1], 16;" :: "r"(saddr), "l"(g));
}
__device__ __forceinline__ void cp_commit() { asm volatile("cp.async.commit_group;"); }
__device__ __forceinline__ void cp_wait1()  { asm volatile("cp.async.wait_group 1;"); }
__device__ __forceinline__ void cp_wait0()  { asm volatile("cp.async.wait_group 0;"); }

// ---------------- kernel D: detect int32 vs int64 layout of x ----------------
__global__ void detect_kernel(const int* __restrict__ xw, int nwords) {
    int i = blockIdx.x * blockDim.x + threadIdx.x;
    int odd = 2 * i + 1;
    if (odd < nwords && xw[odd] != 0) atomicOr(&g_odd_nonzero, 1);
}

// ---------------- kernel P: pack weights + zero state ----------------
__global__ void pack_kernel(const float* __restrict__ W0,
                            const float* __restrict__ W1) {
    size_t i = (size_t)blockIdx.x * blockDim.x + threadIdx.x;
    const size_t N0 = (size_t)GG * HH;        // 1,048,576
    const size_t N1 = (size_t)GG * 2 * HH;    // 2,097,152
    if (i < N0) {
        int c  = (int)(i >> 13);
        int r  = (int)(i & 8191);
        int k4 = r >> 6;
        int cp = (r >> 3) & 7;
        int j  = r & 7;
        int l  = 2 * cp + (j >> 2);
        int k  = 4 * k4 + (j & 3);
        int gcol = ((l >> 2) << 9) + (c << 2) + (l & 3);
        g_Wp0t[i] = W0[(size_t)(EE + k) * GG + gcol];
    }
    if (i < N1) {
        int c  = (int)(i >> 14);
        int r  = (int)(i & 16383);
        int k4 = r >> 6;
        int cp = (r >> 3) & 7;
        int j  = r & 7;
        int l  = 2 * cp + (j >> 2);
        int k  = 4 * k4 + (j & 3);
        int gcol = ((l >> 2) << 9) + (c << 2) + (l & 3);
        g_Wp1t[i] = W1[(size_t)k * GG + gcol];
    }
    if (i < 2 * HB) { g_h0t[i] = 0.0f; g_h1t[i] = 0.0f; }
    if (i == 0) { g_bar_count = 0; g_odd_nonzero = 0; }
}

// ---------------- kernel A: xproj[t][col][b] ----------------
__global__ void __launch_bounds__(256) xproj_kernel(const int* __restrict__ xw,
                                                    const float* __restrict__ emb,
                                                    const float* __restrict__ W0,
                                                    const float* __restrict__ bias0,
                                                    int vmax) {
    __shared__ float s_emb[88 * 128];
    __shared__ int s_row[BB];
    const int t = blockIdx.y;
    const int colbase = blockIdx.x * 128;
    const int tid = threadIdx.x;

    const int stride = g_odd_nonzero ? 1 : 2;
    if (tid < BB) {
        int idx = xw[((size_t)tid * TT + t) * stride];
        idx = idx < 0 ? 0 : (idx > vmax ? vmax : idx);
        s_row[tid] = idx;
    }

    const int cp8 = tid & 15;
    const int bg  = tid >> 4;
    const int cb  = colbase + cp8 * 8;
    const int bi  = bg * 8;

    ull acc[8][4];
#pragma unroll
    for (int c8 = 0; c8 < 8; c8++) {
        ull bv = bcast2(bias0[cb + c8]);
#pragma unroll
        for (int p = 0; p < 4; p++) acc[c8][p] = bv;
    }
    __syncthreads();

    for (int e0 = 0; e0 < EE; e0 += 88) {
        const int ec = (EE - e0 < 88) ? (EE - e0) : 88;
        const int f4cnt = ec >> 2;
        for (int fi = tid; fi < 128 * f4cnt; fi += 256) {
            int b = fi / f4cnt, j = fi % f4cnt;
            const float4 v = *(const float4*)&emb[(size_t)s_row[b] * EE + e0 + j * 4];
            s_emb[(j * 4 + 0) * 128 + b] = v.x;
            s_emb[(j * 4 + 1) * 128 + b] = v.y;
            s_emb[(j * 4 + 2) * 128 + b] = v.z;
            s_emb[(j * 4 + 3) * 128 + b] = v.w;
        }
        __syncthreads();

#pragma unroll 4
        for (int e = 0; e < ec; e++) {
            const float* wrow = W0 + (size_t)(e0 + e) * GG + cb;
            const float4 w0v = *(const float4*)wrow;
            const float4 w1v = *(const float4*)(wrow + 4);
            float wv[8] = {w0v.x, w0v.y, w0v.z, w0v.w, w1v.x, w1v.y, w1v.z, w1v.w};
            const ulonglong2 hA = *(const ulonglong2*)&s_emb[e * 128 + bi];
            const ulonglong2 hB = *(const ulonglong2*)&s_emb[e * 128 + bi + 4];
            ull hp[4] = {hA.x, hA.y, hB.x, hB.y};
#pragma unroll
            for (int c8 = 0; c8 < 8; c8++) {
                ull w2 = bcast2(wv[c8]);
#pragma unroll
                for (int p = 0; p < 4; p++) acc[c8][p] = fma2(hp[p], w2, acc[c8][p]);
            }
        }
        __syncthreads();
    }

#pragma unroll
    for (int c8 = 0; c8 < 8; c8++) {
        size_t base = ((size_t)t * GG + cb + c8) * BB + bi;
#pragma unroll
        for (int p = 0; p < 4; p++)
            *(ull*)&g_xproj[base + p * 2] = acc[c8][p];
    }
}

// ---------------- kernel B: persistent recurrent loop (v3) ----------------
// 128 CTAs x 256 threads. CTA c owns h-cols [4c,4c+4) (16 g-cols per layer).
// Register tile per thread: 2 g-cols x 4 batches per layer -> weight LDG and
// h LDS traffic both halved vs v2 at the same fma2 issue floor.
// Pipelined: iteration t computes L1(t) and L0(t+1) -> one grid barrier/step.
__global__ void __launch_bounds__(256, 1) lstm_kernel(const float* __restrict__ bias1,
                                                      const float* __restrict__ Wd,
                                                      const float* __restrict__ bd,
                                                      float* __restrict__ out) {
    extern __shared__ float smem[];
    float* sbuf[2] = { smem, smem + 8192 };          // 2 x 32KB h chunks [64k][128b]
    float* s_g     = smem + 16384;                   // [16][132] gate staging

    const int c   = blockIdx.x;
    const int tid = threadIdx.x;
    const int cp  = tid & 7;          // col-pair 0..7
    const int bg  = tid >> 3;         // 0..31
    const int b0  = bg * 4;           // 4 batch rows per thread
    const int l0  = 2 * cp, l1 = 2 * cp + 1;
    const int gcl0 = ((l0 >> 2) << 9) + (c << 2) + (l0 & 3);
    const int gcl1 = ((l1 >> 2) << 9) + (c << 2) + (l1 & 3);

    const ull biasA = bcast2(bias1[gcl0]);
    const ull biasB = bcast2(bias1[gcl1]);

    // combine-thread identity: two (q, b) pairs per thread, c-states in regs
    float c0reg[2] = {0.0f, 0.0f}, c1reg[2] = {0.0f, 0.0f};
    int hidx[2], qv[2], bv[2];
#pragma unroll
    for (int rep = 0; rep < 2; rep++) {
        int idx = tid + rep * 256;
        bv[rep] = idx & 127;
        qv[rep] = idx >> 7;          // 0..3
        hidx[rep] = (c * 4 + qv[rep]) * 128 + bv[rep];
    }

    const float4* w0base = (const float4*)g_Wp0t + (size_t)c * 128 * 16;
    const float4* w1base = (const float4*)g_Wp1t + (size_t)c * 256 * 16;

    const uint32_t sb_u32[2] = { (uint32_t)__cvta_generic_to_shared(sbuf[0]),
                                 (uint32_t)__cvta_generic_to_shared(sbuf[1]) };

    // ---- prologue: h0(0) = gates(xproj(0)), c_prev = 0 ----
    {
        size_t xa = ((size_t)0 * GG + gcl0) * BB + b0;
        size_t xb = ((size_t)0 * GG + gcl1) * BB + b0;
        *(ull*)&s_g[l0 * 132 + b0]     = *(const ull*)&g_xproj[xa];
        *(ull*)&s_g[l0 * 132 + b0 + 2] = *(const ull*)&g_xproj[xa + 2];
        *(ull*)&s_g[l1 * 132 + b0]     = *(const ull*)&g_xproj[xb];
        *(ull*)&s_g[l1 * 132 + b0 + 2] = *(const ull*)&g_xproj[xb + 2];
        __syncthreads();
#pragma unroll
        for (int rep = 0; rep < 2; rep++) {
            float gi = s_g[(0 * 4 + qv[rep]) * 132 + bv[rep]];
            float gj = s_g[(1 * 4 + qv[rep]) * 132 + bv[rep]];
            float go = s_g[(3 * 4 + qv[rep]) * 132 + bv[rep]];
            float cn = sigf(gi) * tanhf(gj);       // c_prev = 0
            c0reg[rep] = cn;
            __stcg(&g_h0t[0 * HB + hidx[rep]], tanhf(cn) * sigf(go));
        }
        grid_barrier();
    }

    for (int t = 0; t < TT; t++) {
        const bool  doL0 = (t + 1 < TT);
        const int   tp1  = doL0 ? (t + 1) : t;
        const float* h0src = g_h0t + (t & 1) * HB;           // h0(t)
        const float* h1src = g_h1t + ((t + 1) & 1) * HB;     // h1(t-1)

        // accumulators: [col][pair-of-2-batches]
        ull aL1[2][2] = {{biasA, biasA}, {biasB, biasB}};
        ull aL0[2][2];
        {
            size_t xa = ((size_t)tp1 * GG + gcl0) * BB + b0;
            size_t xb = ((size_t)tp1 * GG + gcl1) * BB + b0;
            aL0[0][0] = __ldcg((const ull*)&g_xproj[xa]);
            aL0[0][1] = __ldcg((const ull*)&g_xproj[xa + 2]);
            aL0[1][0] = __ldcg((const ull*)&g_xproj[xb]);
            aL0[1][1] = __ldcg((const ull*)&g_xproj[xb + 2]);
        }

        // prime pipeline: chunk 0
        {
            const float* g = h0src;
#pragma unroll
            for (int p = 0; p < 8; p++) cp16(sb_u32[0] + (p * 256 + tid) * 16, g + (p * 256 + tid) * 4);
            cp_commit();
        }

        for (int ch = 0; ch < 16; ch++) {
            if (ch < 15) {
                const float* g = (ch + 1 < 8) ? (h0src + (ch + 1) * 8192)
                                              : (h1src + (ch + 1 - 8) * 8192);
                uint32_t sa = sb_u32[(ch + 1) & 1];
#pragma unroll
                for (int p = 0; p < 8; p++) cp16(sa + (p * 256 + tid) * 16, g + (p * 256 + tid) * 4);
                cp_commit();
                cp_wait1();
            } else {
                cp_wait0();
            }
            __syncthreads();
            const float* sh = sbuf[ch & 1];

            if (ch < 8) {
                const float4* w0p = w0base + ((size_t)(ch * 16) * 8 + cp) * 2;
                const float4* w1p = w1base + ((size_t)(ch * 16) * 8 + cp) * 2;
#pragma unroll 4
                for (int j = 0; j < 16; j++) {
                    const float4 wA = w0p[j * 16 + 0];
                    const float4 wB = w0p[j * 16 + 1];
                    const float4 wC = w1p[j * 16 + 0];
                    const float4 wD = w1p[j * 16 + 1];
                    const float wAv[4] = {wA.x, wA.y, wA.z, wA.w};
                    const float wBv[4] = {wB.x, wB.y, wB.z, wB.w};
                    const float wCv[4] = {wC.x, wC.y, wC.z, wC.w};
                    const float wDv[4] = {wD.x, wD.y, wD.z, wD.w};
#pragma unroll
                    for (int kk = 0; kk < 4; kk++) {
                        const ulonglong2 h2 = *(const ulonglong2*)&sh[(j * 4 + kk) * 128 + b0];
                        ull wa = bcast2(wAv[kk]), wb = bcast2(wBv[kk]);
                        ull wc = bcast2(wCv[kk]), wd = bcast2(wDv[kk]);
                        aL0[0][0] = fma2(h2.x, wa, aL0[0][0]);
                        aL0[0][1] = fma2(h2.y, wa, aL0[0][1]);
                        aL0[1][0] = fma2(h2.x, wb, aL0[1][0]);
                        aL0[1][1] = fma2(h2.y, wb, aL0[1][1]);
                        aL1[0][0] = fma2(h2.x, wc, aL1[0][0]);
                        aL1[0][1] = fma2(h2.y, wc, aL1[0][1]);
                        aL1[1][0] = fma2(h2.x, wd, aL1[1][0]);
                        aL1[1][1] = fma2(h2.y, wd, aL1[1][1]);
                    }
                }
            } else {
                const float4* w1p = w1base + ((size_t)(128 + (ch - 8) * 16) * 8 + cp) * 2;
#pragma unroll 4
                for (int j = 0; j < 16; j++) {
                    const float4 wC = w1p[j * 16 + 0];
                    const float4 wD = w1p[j * 16 + 1];
                    const float wCv[4] = {wC.x, wC.y, wC.z, wC.w};
                    const float wDv[4] = {wD.x, wD.y, wD.z, wD.w};
#pragma unroll
                    for (int kk = 0; kk < 4; kk++) {
                        const ulonglong2 h2 = *(const ulonglong2*)&sh[(j * 4 + kk) * 128 + b0];
                        ull wc = bcast2(wCv[kk]), wd = bcast2(wDv[kk]);
                        aL1[0][0] = fma2(h2.x, wc, aL1[0][0]);
                        aL1[0][1] = fma2(h2.y, wc, aL1[0][1]);
                        aL1[1][0] = fma2(h2.x, wd, aL1[1][0]);
                        aL1[1][1] = fma2(h2.y, wd, aL1[1][1]);
                    }
                }
            }
            __syncthreads();
        }

        // ---- L1(t) gates -> h1(t) ----
        *(ull*)&s_g[l0 * 132 + b0]     = aL1[0][0];
        *(ull*)&s_g[l0 * 132 + b0 + 2] = aL1[0][1];
        *(ull*)&s_g[l1 * 132 + b0]     = aL1[1][0];
        *(ull*)&s_g[l1 * 132 + b0 + 2] = aL1[1][1];
        __syncthreads();
#pragma unroll
        for (int rep = 0; rep < 2; rep++) {
            float gi = s_g[(0 * 4 + qv[rep]) * 132 + bv[rep]];
            float gj = s_g[(1 * 4 + qv[rep]) * 132 + bv[rep]];
            float gf = s_g[(2 * 4 + qv[rep]) * 132 + bv[rep]];
            float go = s_g[(3 * 4 + qv[rep]) * 132 + bv[rep]];
            float cn = c1reg[rep] * sigf(gf + 1.0f) + sigf(gi) * tanhf(gj);
            c1reg[rep] = cn;
            __stcg(&g_h1t[(t & 1) * HB + hidx[rep]], tanhf(cn) * sigf(go));
        }
        __syncthreads();

        // ---- L0(t+1) gates -> h0(t+1) ----
        if (doL0) {
            *(ull*)&s_g[l0 * 132 + b0]     = aL0[0][0];
            *(ull*)&s_g[l0 * 132 + b0 + 2] = aL0[0][1];
            *(ull*)&s_g[l1 * 132 + b0]     = aL0[1][0];
            *(ull*)&s_g[l1 * 132 + b0 + 2] = aL0[1][1];
            __syncthreads();
#pragma unroll
            for (int rep = 0; rep < 2; rep++) {
                float gi = s_g[(0 * 4 + qv[rep]) * 132 + bv[rep]];
                float gj = s_g[(1 * 4 + qv[rep]) * 132 + bv[rep]];
                float gf = s_g[(2 * 4 + qv[rep]) * 132 + bv[rep]];
                float go = s_g[(3 * 4 + qv[rep]) * 132 + bv[rep]];
                float cn = c0reg[rep] * sigf(gf + 1.0f) + sigf(gi) * tanhf(gj);
                c0reg[rep] = cn;
                __stcg(&g_h0t[((t + 1) & 1) * HB + hidx[rep]], tanhf(cn) * sigf(go));
            }
        }
        grid_barrier();
    }

    // ---- final projection: logits = h1(T-1) . Wd + bd ----
    if (blockIdx.x == 0) {
        const int b = tid & 127, oc = tid >> 7;
        const float* hf = g_h1t + ((TT - 1) & 1) * HB;
        float s = 0.0f;
#pragma unroll 8
        for (int k = 0; k < HH; k++)
            s += __ldcg(&hf[k * 128 + b]) * Wd[k * 2 + oc];
        out[b * 2 + oc] = s + bd[oc];
    }
}

// ---------------- launch ----------------
extern "C" void kernel_launch(void* const* d_in, const int* in_sizes, int n_in,
                              void* d_out, int out_size) {
    const int* xw    = (const int*)d_in[0];
    const float* emb = (const float*)d_in[1];
    const float* W0  = (const float*)d_in[2];
    const float* b0  = (const float*)d_in[3];
    const float* W1  = (const float*)d_in[4];
    const float* b1  = (const float*)d_in[5];
    const float* Wd  = (const float*)d_in[6];
    const float* bd  = (const float*)d_in[7];
    float* out       = (float*)d_out;
    (void)n_in; (void)out_size;

    const int nx   = in_sizes[0];
    const int vmax = in_sizes[1] / EE - 1;

    const int smemBytes = (2 * 8192 + 16 * 132) * sizeof(float);   // 73984
    cudaFuncSetAttribute(lstm_kernel, cudaFuncAttributeMaxDynamicSharedMemorySize, smemBytes);

    pack_kernel<<<8192, 256>>>(W0, W1);
    detect_kernel<<<(nx / 2 + 255) / 256, 256>>>(xw, nx);
    xproj_kernel<<<dim3(16, TT), 256>>>(xw, emb, W0, b0, vmax);
    lstm_kernel<<<BB, 256, smemBytes>>>(b1, Wd, bd, out);
}

// round 11
// speedup vs baseline: 1.8398x; 1.8398x over previous
#include <cuda_runtime.h>
#include <cstdint>
#include <math.h>

#define BB   128      // batch
#define TT   256      // timesteps
#define HH   512      // hidden
#define EE   300      // embed dim
#define GG   2048     // 4H
#define HB   (HH*BB)  // one h buffer (transposed [k][b]) = 65536 floats

// ---------------- device scratch (static, no allocation) ----------------
__device__ float g_xproj[(size_t)TT * GG * BB];   // [t][col][b]  256MB
__device__ float g_Wp0t[(size_t)GG * HH];         // [c][k4:128][cp:8][2cols x 4k]
__device__ float g_Wp1t[(size_t)GG * 2 * HH];     // [c][k4:256][cp:8][2cols x 4k]
__device__ float g_h0t[2 * HB];                   // transposed [k][b], ping-pong
__device__ float g_h1t[2 * HB];
__device__ unsigned g_bar_count;
__device__ unsigned g_bar_gen;
__device__ int g_odd_nonzero;                     // 1 -> x buffer is int32 layout

// ---------------- helpers ----------------
typedef unsigned long long ull;

__device__ __forceinline__ ull bcast2(float v) {
    ull r; asm("mov.b64 %0, {%1, %1};" : "=l"(r) : "f"(v)); return r;
}
__device__ __forceinline__ ull fma2(ull a, ull b, ull c) {
    ull d; asm("fma.rn.f32x2 %0, %1, %2, %3;" : "=l"(d) : "l"(a), "l"(b), "l"(c)); return d;
}
__device__ __forceinline__ ull add2(ull a, ull b) {
    ull d; asm("add.rn.f32x2 %0, %1, %2;" : "=l"(d) : "l"(a), "l"(b)); return d;
}
__device__ __forceinline__ float sigf(float x) { return 1.0f / (1.0f + expf(-x)); }

__device__ __forceinline__ void grid_barrier() {
    __syncthreads();
    if (threadIdx.x == 0) {
        __threadfence();
        unsigned gen = *((volatile unsigned*)&g_bar_gen);
        unsigned ticket = atomicAdd(&g_bar_count, 1u);
        if (ticket == gridDim.x - 1) {
            atomicExch(&g_bar_count, 0u);
            __threadfence();
            atomicAdd(&g_bar_gen, 1u);
        } else {
            while (*((volatile unsigned*)&g_bar_gen) == gen) {}
            __threadfence();
        }
    }
    __syncthreads();
}

__device__ __forceinline__ void cp16(uint32_t saddr, const float* g) {
    asm volatile("cp.async.cg.shared.global [%0], [%1], 16;" :: "r"(saddr), "l"(g));
}
__device__ __forceinline__ void cp_commit() { asm volatile("cp.async.commit_group;"); }
__device__ __forceinline__ void cp_wait1()  { asm volatile("cp.async.wait_group 1;"); }
__device__ __forceinline__ void cp_wait0()  { asm volatile("cp.async.wait_group 0;"); }

// ---------------- kernel D: detect int32 vs int64 layout of x ----------------
__global__ void detect_kernel(const int* __restrict__ xw, int nwords) {
    int i = blockIdx.x * blockDim.x + threadIdx.x;
    int odd = 2 * i + 1;
    if (odd < nwords && xw[odd] != 0) atomicOr(&g_odd_nonzero, 1);
}

// ---------------- kernel P: pack weights + zero state ----------------
__global__ void pack_kernel(const float* __restrict__ W0,
                            const float* __restrict__ W1) {
    size_t i = (size_t)blockIdx.x * blockDim.x + threadIdx.x;
    const size_t N0 = (size_t)GG * HH;        // 1,048,576
    const size_t N1 = (size_t)GG * 2 * HH;    // 2,097,152
    if (i < N0) {
        int c  = (int)(i >> 13);
        int r  = (int)(i & 8191);
        int k4 = r >> 6;
        int cp = (r >> 3) & 7;
        int j  = r & 7;
        int l  = 2 * cp + (j >> 2);
        int k  = 4 * k4 + (j & 3);
        int gcol = ((l >> 2) << 9) + (c << 2) + (l & 3);
        g_Wp0t[i] = W0[(size_t)(EE + k) * GG + gcol];
    }
    if (i < N1) {
        int c  = (int)(i >> 14);
        int r  = (int)(i & 16383);
        int k4 = r >> 6;
        int cp = (r >> 3) & 7;
        int j  = r & 7;
        int l  = 2 * cp + (j >> 2);
        int k  = 4 * k4 + (j & 3);
        int gcol = ((l >> 2) << 9) + (c << 2) + (l & 3);
        g_Wp1t[i] = W1[(size_t)k * GG + gcol];
    }
    if (i < 2 * HB) { g_h0t[i] = 0.0f; g_h1t[i] = 0.0f; }
    if (i == 0) { g_bar_count = 0; g_odd_nonzero = 0; }
}

// ---------------- kernel A: xproj[t][col][b] ----------------
__global__ void __launch_bounds__(256) xproj_kernel(const int* __restrict__ xw,
                                                    const float* __restrict__ emb,
                                                    const float* __restrict__ W0,
                                                    const float* __restrict__ bias0,
                                                    int vmax) {
    __shared__ float s_emb[88 * 128];
    __shared__ int s_row[BB];
    const int t = blockIdx.y;
    const int colbase = blockIdx.x * 128;
    const int tid = threadIdx.x;

    const int stride = g_odd_nonzero ? 1 : 2;
    if (tid < BB) {
        int idx = xw[((size_t)tid * TT + t) * stride];
        idx = idx < 0 ? 0 : (idx > vmax ? vmax : idx);
        s_row[tid] = idx;
    }

    const int cp8 = tid & 15;
    const int bg  = tid >> 4;
    const int cb  = colbase + cp8 * 8;
    const int bi  = bg * 8;

    ull acc[8][4];
#pragma unroll
    for (int c8 = 0; c8 < 8; c8++) {
        ull bv = bcast2(bias0[cb + c8]);
#pragma unroll
        for (int p = 0; p < 4; p++) acc[c8][p] = bv;
    }
    __syncthreads();

    for (int e0 = 0; e0 < EE; e0 += 88) {
        const int ec = (EE - e0 < 88) ? (EE - e0) : 88;
        const int f4cnt = ec >> 2;
        for (int fi = tid; fi < 128 * f4cnt; fi += 256) {
            int b = fi / f4cnt, j = fi % f4cnt;
            const float4 v = *(const float4*)&emb[(size_t)s_row[b] * EE + e0 + j * 4];
            s_emb[(j * 4 + 0) * 128 + b] = v.x;
            s_emb[(j * 4 + 1) * 128 + b] = v.y;
            s_emb[(j * 4 + 2) * 128 + b] = v.z;
            s_emb[(j * 4 + 3) * 128 + b] = v.w;
        }
        __syncthreads();

#pragma unroll 4
        for (int e = 0; e < ec; e++) {
            const float* wrow = W0 + (size_t)(e0 + e) * GG + cb;
            const float4 w0v = *(const float4*)wrow;
            const float4 w1v = *(const float4*)(wrow + 4);
            float wv[8] = {w0v.x, w0v.y, w0v.z, w0v.w, w1v.x, w1v.y, w1v.z, w1v.w};
            const ulonglong2 hA = *(const ulonglong2*)&s_emb[e * 128 + bi];
            const ulonglong2 hB = *(const ulonglong2*)&s_emb[e * 128 + bi + 4];
            ull hp[4] = {hA.x, hA.y, hB.x, hB.y};
#pragma unroll
            for (int c8 = 0; c8 < 8; c8++) {
                ull w2 = bcast2(wv[c8]);
#pragma unroll
                for (int p = 0; p < 4; p++) acc[c8][p] = fma2(hp[p], w2, acc[c8][p]);
            }
        }
        __syncthreads();
    }

#pragma unroll
    for (int c8 = 0; c8 < 8; c8++) {
        size_t base = ((size_t)t * GG + cb + c8) * BB + bi;
#pragma unroll
        for (int p = 0; p < 4; p++)
            *(ull*)&g_xproj[base + p * 2] = acc[c8][p];
    }
}

// ---------------- kernel B: persistent recurrent loop (v4.1) ----------------
// 128 CTAs x 512 threads. Two independent 256-thread halves split the
// k-dimension (alternating 64-k chunks), each with private double-buffer +
// private named barrier -> 16 warps/SM concurrently active. Per-step f32x2
// smem reduction merges partials. One grid barrier per step.
// v4.1 fix: reduction scratch is 4096 floats (256 thr x 8 ull), was 2048.
__global__ void __launch_bounds__(512, 1) lstm_kernel(const float* __restrict__ bias1,
                                                      const float* __restrict__ Wd,
                                                      const float* __restrict__ bd,
                                                      float* __restrict__ out) {
    extern __shared__ float smem[];
    // layout: half A slots [0,8192),[8192,16384); half B slots [16384,24576),[24576,32768)
    float* s_g   = smem + 32768;                 // [16][132] gate staging (2112 f)
    ull*   s_red = (ull*)(smem + 34880);         // 256 threads x 8 ull = 4096 f

    const int c   = blockIdx.x;
    const int tid = threadIdx.x;
    const int hb  = tid >> 8;         // half id: 0 or 1
    const int tl  = tid & 255;        // lane within half
    const int cp  = tl & 7;           // col-pair 0..7
    const int bg  = tl >> 3;          // 0..31
    const int b0  = bg * 4;           // 4 batch rows per thread
    const int l0  = 2 * cp, l1 = 2 * cp + 1;
    const int gcl0 = ((l0 >> 2) << 9) + (c << 2) + (l0 & 3);
    const int gcl1 = ((l1 >> 2) << 9) + (c << 2) + (l1 & 3);

    const ull biasA = bcast2(bias1[gcl0]);
    const ull biasB = bcast2(bias1[gcl1]);

    // combine-thread identity (half A only does gates)
    float c0reg[2] = {0.0f, 0.0f}, c1reg[2] = {0.0f, 0.0f};
    int hidx[2], qv[2], bv[2];
#pragma unroll
    for (int rep = 0; rep < 2; rep++) {
        int idx = tl + rep * 256;
        bv[rep] = idx & 127;
        qv[rep] = idx >> 7;
        hidx[rep] = (c * 4 + qv[rep]) * 128 + bv[rep];
    }

    const float4* w0base = (const float4*)g_Wp0t + (size_t)c * 128 * 16;
    const float4* w1base = (const float4*)g_Wp1t + (size_t)c * 256 * 16;

    float* mybuf[2] = { smem + hb * 16384, smem + hb * 16384 + 8192 };
    const uint32_t sb_u32[2] = { (uint32_t)__cvta_generic_to_shared(mybuf[0]),
                                 (uint32_t)__cvta_generic_to_shared(mybuf[1]) };

    // ---- prologue: h0(0) = gates(xproj(0)), c_prev = 0 ----
    if (hb == 0) {
        size_t xa = ((size_t)0 * GG + gcl0) * BB + b0;
        size_t xb = ((size_t)0 * GG + gcl1) * BB + b0;
        *(ull*)&s_g[l0 * 132 + b0]     = *(const ull*)&g_xproj[xa];
        *(ull*)&s_g[l0 * 132 + b0 + 2] = *(const ull*)&g_xproj[xa + 2];
        *(ull*)&s_g[l1 * 132 + b0]     = *(const ull*)&g_xproj[xb];
        *(ull*)&s_g[l1 * 132 + b0 + 2] = *(const ull*)&g_xproj[xb + 2];
    }
    __syncthreads();
    if (hb == 0) {
#pragma unroll
        for (int rep = 0; rep < 2; rep++) {
            float gi = s_g[(0 * 4 + qv[rep]) * 132 + bv[rep]];
            float gj = s_g[(1 * 4 + qv[rep]) * 132 + bv[rep]];
            float go = s_g[(3 * 4 + qv[rep]) * 132 + bv[rep]];
            float cn = sigf(gi) * tanhf(gj);       // c_prev = 0
            c0reg[rep] = cn;
            __stcg(&g_h0t[0 * HB + hidx[rep]], tanhf(cn) * sigf(go));
        }
    }
    grid_barrier();

    for (int t = 0; t < TT; t++) {
        const bool  doL0 = (t + 1 < TT);
        const int   tp1  = doL0 ? (t + 1) : t;
        const float* h0src = g_h0t + (t & 1) * HB;           // h0(t)
        const float* h1src = g_h1t + ((t + 1) & 1) * HB;     // h1(t-1)

        // accumulators: [col][pair-of-2-batches]; half A carries bias/xproj
        ull aL1[2][2], aL0[2][2];
        if (hb == 0) {
            aL1[0][0] = biasA; aL1[0][1] = biasA;
            aL1[1][0] = biasB; aL1[1][1] = biasB;
            size_t xa = ((size_t)tp1 * GG + gcl0) * BB + b0;
            size_t xb = ((size_t)tp1 * GG + gcl1) * BB + b0;
            aL0[0][0] = __ldcg((const ull*)&g_xproj[xa]);
            aL0[0][1] = __ldcg((const ull*)&g_xproj[xa + 2]);
            aL0[1][0] = __ldcg((const ull*)&g_xproj[xb]);
            aL0[1][1] = __ldcg((const ull*)&g_xproj[xb + 2]);
        } else {
            aL1[0][0] = 0ull; aL1[0][1] = 0ull; aL1[1][0] = 0ull; aL1[1][1] = 0ull;
            aL0[0][0] = 0ull; aL0[0][1] = 0ull; aL0[1][0] = 0ull; aL0[1][1] = 0ull;
        }

        // prime: my chunk 0 (global chunk hb)
        {
            const float* g = h0src + hb * 8192;
#pragma unroll
            for (int p = 0; p < 8; p++) cp16(sb_u32[0] + (p * 256 + tl) * 16, g + (p * 256 + tl) * 4);
            cp_commit();
        }

        for (int i = 0; i < 8; i++) {
            const int ch = 2 * i + hb;                       // my global chunk
            if (i < 7) {
                const int nch = ch + 2;
                const float* g = (nch < 8) ? (h0src + nch * 8192)
                                           : (h1src + (nch - 8) * 8192);
                const uint32_t sa = sb_u32[(i + 1) & 1];
#pragma unroll
                for (int p = 0; p < 8; p++) cp16(sa + (p * 256 + tl) * 16, g + (p * 256 + tl) * 4);
                cp_commit();
                cp_wait1();
            } else {
                cp_wait0();
            }
            asm volatile("bar.sync %0, 256;" :: "r"(1 + hb) : "memory");
            const float* sh = mybuf[i & 1];

            if (ch < 8) {
                const float4* w0p = w0base + ((size_t)(ch * 16) * 8 + cp) * 2;
                const float4* w1p = w1base + ((size_t)(ch * 16) * 8 + cp) * 2;
#pragma unroll 4
                for (int j = 0; j < 16; j++) {
                    const float4 wA = w0p[j * 16 + 0];
                    const float4 wB = w0p[j * 16 + 1];
                    const float4 wC = w1p[j * 16 + 0];
                    const float4 wD = w1p[j * 16 + 1];
                    const float wAv[4] = {wA.x, wA.y, wA.z, wA.w};
                    const float wBv[4] = {wB.x, wB.y, wB.z, wB.w};
                    const float wCv[4] = {wC.x, wC.y, wC.z, wC.w};
                    const float wDv[4] = {wD.x, wD.y, wD.z, wD.w};
#pragma unroll
                    for (int kk = 0; kk < 4; kk++) {
                        const ulonglong2 h2 = *(const ulonglong2*)&sh[(j * 4 + kk) * 128 + b0];
                        ull wa = bcast2(wAv[kk]), wb = bcast2(wBv[kk]);
                        ull wc = bcast2(wCv[kk]), wd = bcast2(wDv[kk]);
                        aL0[0][0] = fma2(h2.x, wa, aL0[0][0]);
                        aL0[0][1] = fma2(h2.y, wa, aL0[0][1]);
                        aL0[1][0] = fma2(h2.x, wb, aL0[1][0]);
                        aL0[1][1] = fma2(h2.y, wb, aL0[1][1]);
                        aL1[0][0] = fma2(h2.x, wc, aL1[0][0]);
                        aL1[0][1] = fma2(h2.y, wc, aL1[0][1]);
                        aL1[1][0] = fma2(h2.x, wd, aL1[1][0]);
                        aL1[1][1] = fma2(h2.y, wd, aL1[1][1]);
                    }
                }
            } else {
                const float4* w1p = w1base + ((size_t)(128 + (ch - 8) * 16) * 8 + cp) * 2;
#pragma unroll 4
                for (int j = 0; j < 16; j++) {
                    const float4 wC = w1p[j * 16 + 0];
                    const float4 wD = w1p[j * 16 + 1];
                    const float wCv[4] = {wC.x, wC.y, wC.z, wC.w};
                    const float wDv[4] = {wD.x, wD.y, wD.z, wD.w};
#pragma unroll
                    for (int kk = 0; kk < 4; kk++) {
                        const ulonglong2 h2 = *(const ulonglong2*)&sh[(j * 4 + kk) * 128 + b0];
                        ull wc = bcast2(wCv[kk]), wd = bcast2(wDv[kk]);
                        aL1[0][0] = fma2(h2.x, wc, aL1[0][0]);
                        aL1[0][1] = fma2(h2.y, wc, aL1[0][1]);
                        aL1[1][0] = fma2(h2.x, wd, aL1[1][0]);
                        aL1[1][1] = fma2(h2.y, wd, aL1[1][1]);
                    }
                }
            }
            asm volatile("bar.sync %0, 256;" :: "r"(1 + hb) : "memory");
        }

        // ---- reduce half-B partials into half A ----
        if (hb == 1) {
            ull* r = s_red + tl * 8;
            ((ulonglong2*)r)[0] = make_ulonglong2(aL1[0][0], aL1[0][1]);
            ((ulonglong2*)r)[1] = make_ulonglong2(aL1[1][0], aL1[1][1]);
            ((ulonglong2*)r)[2] = make_ulonglong2(aL0[0][0], aL0[0][1]);
            ((ulonglong2*)r)[3] = make_ulonglong2(aL0[1][0], aL0[1][1]);
        }
        __syncthreads();
        if (hb == 0) {
            const ull* r = s_red + tl * 8;
            aL1[0][0] = add2(aL1[0][0], r[0]); aL1[0][1] = add2(aL1[0][1], r[1]);
            aL1[1][0] = add2(aL1[1][0], r[2]); aL1[1][1] = add2(aL1[1][1], r[3]);
            aL0[0][0] = add2(aL0[0][0], r[4]); aL0[0][1] = add2(aL0[0][1], r[5]);
            aL0[1][0] = add2(aL0[1][0], r[6]); aL0[1][1] = add2(aL0[1][1], r[7]);

            // ---- L1(t) gates -> h1(t) ----
            *(ull*)&s_g[l0 * 132 + b0]     = aL1[0][0];
            *(ull*)&s_g[l0 * 132 + b0 + 2] = aL1[0][1];
            *(ull*)&s_g[l1 * 132 + b0]     = aL1[1][0];
            *(ull*)&s_g[l1 * 132 + b0 + 2] = aL1[1][1];
        }
        __syncthreads();
        if (hb == 0) {
#pragma unroll
            for (int rep = 0; rep < 2; rep++) {
                float gi = s_g[(0 * 4 + qv[rep]) * 132 + bv[rep]];
                float gj = s_g[(1 * 4 + qv[rep]) * 132 + bv[rep]];
                float gf = s_g[(2 * 4 + qv[rep]) * 132 + bv[rep]];
                float go = s_g[(3 * 4 + qv[rep]) * 132 + bv[rep]];
                float cn = c1reg[rep] * sigf(gf + 1.0f) + sigf(gi) * tanhf(gj);
                c1reg[rep] = cn;
                __stcg(&g_h1t[(t & 1) * HB + hidx[rep]], tanhf(cn) * sigf(go));
            }
        }
        __syncthreads();

        // ---- L0(t+1) gates -> h0(t+1) ----
        if (doL0) {
            if (hb == 0) {
                *(ull*)&s_g[l0 * 132 + b0]     = aL0[0][0];
                *(ull*)&s_g[l0 * 132 + b0 + 2] = aL0[0][1];
                *(ull*)&s_g[l1 * 132 + b0]     = aL0[1][0];
                *(ull*)&s_g[l1 * 132 + b0 + 2] = aL0[1][1];
            }
            __syncthreads();
            if (hb == 0) {
#pragma unroll
                for (int rep = 0; rep < 2; rep++) {
                    float gi = s_g[(0 * 4 + qv[rep]) * 132 + bv[rep]];
                    float gj = s_g[(1 * 4 + qv[rep]) * 132 + bv[rep]];
                    float gf = s_g[(2 * 4 + qv[rep]) * 132 + bv[rep]];
                    float go = s_g[(3 * 4 + qv[rep]) * 132 + bv[rep]];
                    float cn = c0reg[rep] * sigf(gf + 1.0f) + sigf(gi) * tanhf(gj);
                    c0reg[rep] = cn;
                    __stcg(&g_h0t[((t + 1) & 1) * HB + hidx[rep]], tanhf(cn) * sigf(go));
                }
            }
        }
        grid_barrier();
    }

    // ---- final projection: logits = h1(T-1) . Wd + bd ----
    if (blockIdx.x == 0 && tid < 256) {
        const int b = tid & 127, oc = tid >> 7;
        const float* hf = g_h1t + ((TT - 1) & 1) * HB;
        float s = 0.0f;
#pragma unroll 8
        for (int k = 0; k < HH; k++)
            s += __ldcg(&hf[k * 128 + b]) * Wd[k * 2 + oc];
        out[b * 2 + oc] = s + bd[oc];
    }
}

// ---------------- launch ----------------
extern "C" void kernel_launch(void* const* d_in, const int* in_sizes, int n_in,
                              void* d_out, int out_size) {
    const int* xw    = (const int*)d_in[0];
    const float* emb = (const float*)d_in[1];
    const float* W0  = (const float*)d_in[2];
    const float* b0  = (const float*)d_in[3];
    const float* W1  = (const float*)d_in[4];
    const float* b1  = (const float*)d_in[5];
    const float* Wd  = (const float*)d_in[6];
    const float* bd  = (const float*)d_in[7];
    float* out       = (float*)d_out;
    (void)n_in; (void)out_size;

    const int nx   = in_sizes[0];
    const int vmax = in_sizes[1] / EE - 1;

    // 4 x 32KB h slots + gate staging (2112 f) + reduction (4096 f)  [v4.1 fix]
    const int smemBytes = (32768 + 2112 + 4096) * sizeof(float);   // 155904
    cudaFuncSetAttribute(lstm_kernel, cudaFuncAttributeMaxDynamicSharedMemorySize, smemBytes);

    pack_kernel<<<8192, 256>>>(W0, W1);
    detect_kernel<<<(nx / 2 + 255) / 256, 256>>>(xw, nx);
    xproj_kernel<<<dim3(16, TT), 256>>>(xw, emb, W0, b0, vmax);
    lstm_kernel<<<BB, 512, smemBytes>>>(b1, Wd, bd, out);
}

// round 13
// speedup vs baseline: 2.8501x; 1.5491x over previous
#include <cuda_runtime.h>
#include <cstdint>
#include <math.h>

#define BB   128      // batch
#define TT   256      // timesteps
#define HH   512      // hidden
#define EE   300      // embed dim
#define GG   2048     // 4H
#define HB   (HH*BB)

// ---------------- device scratch (static, no allocation) ----------------
__device__ float g_xproj[(size_t)TT * GG * BB];      // [t][col][b]  256MB
__device__ float g_Wq0[(size_t)128 * 512 * 16];      // [c][k][l]  4MB
__device__ float g_Wq1[(size_t)128 * 1024 * 16];     // [c][k][l]  8MB
__device__ float g_h0t[2 * HB];                      // transposed [k][b], ping-pong
__device__ float g_h1t[2 * HB];
__device__ unsigned g_bar_count;
__device__ unsigned g_bar_gen;
__device__ int g_odd_nonzero;

// ---------------- helpers ----------------
typedef unsigned long long ull;

__device__ __forceinline__ ull bcast2(float v) {
    ull r; asm("mov.b64 %0, {%1, %1};" : "=l"(r) : "f"(v)); return r;
}
__device__ __forceinline__ ull fma2(ull a, ull b, ull c) {
    ull d; asm("fma.rn.f32x2 %0, %1, %2, %3;" : "=l"(d) : "l"(a), "l"(b), "l"(c)); return d;
}
__device__ __forceinline__ ull add2(ull a, ull b) {
    ull d; asm("add.rn.f32x2 %0, %1, %2;" : "=l"(d) : "l"(a), "l"(b)); return d;
}
__device__ __forceinline__ float2 unpk2(ull v) {
    float2 f; asm("mov.b64 {%0, %1}, %2;" : "=f"(f.x), "=f"(f.y) : "l"(v)); return f;
}
__device__ __forceinline__ float sigf(float x) { return 1.0f / (1.0f + expf(-x)); }

__device__ __forceinline__ void grid_barrier() {
    __syncthreads();
    if (threadIdx.x == 0) {
        __threadfence();
        unsigned gen = *((volatile unsigned*)&g_bar_gen);
        unsigned ticket = atomicAdd(&g_bar_count, 1u);
        if (ticket == gridDim.x - 1) {
            atomicExch(&g_bar_count, 0u);
            __threadfence();
            atomicAdd(&g_bar_gen, 1u);
        } else {
            while (*((volatile unsigned*)&g_bar_gen) == gen) {}
            __threadfence();
        }
    }
    __syncthreads();
}

__device__ __forceinline__ void cp16(uint32_t saddr, const float* g) {
    asm volatile("cp.async.cg.shared.global [%0], [%1], 16;" :: "r"(saddr), "l"(g));
}
__device__ __forceinline__ void cp_commit() { asm volatile("cp.async.commit_group;"); }
__device__ __forceinline__ void cp_wait1()  { asm volatile("cp.async.wait_group 1;"); }
__device__ __forceinline__ void cp_wait0()  { asm volatile("cp.async.wait_group 0;"); }

// ---------------- kernel D: detect int32 vs int64 layout of x ----------------
__global__ void detect_kernel(const int* __restrict__ xw, int nwords) {
    int i = blockIdx.x * blockDim.x + threadIdx.x;
    int odd = 2 * i + 1;
    if (odd < nwords && xw[odd] != 0) atomicOr(&g_odd_nonzero, 1);
}

// ---------------- kernel P: pack weights [c][k][l] + zero state ----------------
// l -> gcol = (l>>2)*512 + c*4 + (l&3)   (gate = l>>2, hcol = l&3)
__global__ void pack_kernel(const float* __restrict__ W0,
                            const float* __restrict__ W1) {
    size_t i = (size_t)blockIdx.x * blockDim.x + threadIdx.x;
    const size_t N0 = (size_t)128 * 512 * 16;    // 1,048,576
    const size_t N1 = (size_t)128 * 1024 * 16;   // 2,097,152
    if (i < N0) {
        int c = (int)(i >> 13);
        int r = (int)(i & 8191);
        int k = r >> 4, l = r & 15;
        int gcol = ((l >> 2) << 9) + (c << 2) + (l & 3);
        g_Wq0[i] = W0[(size_t)(EE + k) * GG + gcol];
    }
    if (i < N1) {
        int c = (int)(i >> 14);
        int r = (int)(i & 16383);
        int k = r >> 4, l = r & 15;
        int gcol = ((l >> 2) << 9) + (c << 2) + (l & 3);
        g_Wq1[i] = W1[(size_t)k * GG + gcol];
    }
    if (i < 2 * HB) { g_h0t[i] = 0.0f; g_h1t[i] = 0.0f; }
    if (i == 0) { g_bar_count = 0; g_odd_nonzero = 0; }
}

// ---------------- kernel A: xproj[t][col][b] ----------------
__global__ void __launch_bounds__(256) xproj_kernel(const int* __restrict__ xw,
                                                    const float* __restrict__ emb,
                                                    const float* __restrict__ W0,
                                                    const float* __restrict__ bias0,
                                                    int vmax) {
    __shared__ float s_emb[88 * 128];
    __shared__ int s_row[BB];
    const int t = blockIdx.y;
    const int colbase = blockIdx.x * 128;
    const int tid = threadIdx.x;

    const int stride = g_odd_nonzero ? 1 : 2;
    if (tid < BB) {
        int idx = xw[((size_t)tid * TT + t) * stride];
        idx = idx < 0 ? 0 : (idx > vmax ? vmax : idx);
        s_row[tid] = idx;
    }

    const int cp8 = tid & 15;
    const int bg  = tid >> 4;
    const int cb  = colbase + cp8 * 8;
    const int bi  = bg * 8;

    ull acc[8][4];
#pragma unroll
    for (int c8 = 0; c8 < 8; c8++) {
        ull bv = bcast2(bias0[cb + c8]);
#pragma unroll
        for (int p = 0; p < 4; p++) acc[c8][p] = bv;
    }
    __syncthreads();

    for (int e0 = 0; e0 < EE; e0 += 88) {
        const int ec = (EE - e0 < 88) ? (EE - e0) : 88;
        const int f4cnt = ec >> 2;
        for (int fi = tid; fi < 128 * f4cnt; fi += 256) {
            int b = fi / f4cnt, j = fi % f4cnt;
            const float4 v = *(const float4*)&emb[(size_t)s_row[b] * EE + e0 + j * 4];
            s_emb[(j * 4 + 0) * 128 + b] = v.x;
            s_emb[(j * 4 + 1) * 128 + b] = v.y;
            s_emb[(j * 4 + 2) * 128 + b] = v.z;
            s_emb[(j * 4 + 3) * 128 + b] = v.w;
        }
        __syncthreads();

#pragma unroll 4
        for (int e = 0; e < ec; e++) {
            const float* wrow = W0 + (size_t)(e0 + e) * GG + cb;
            const float4 w0v = *(const float4*)wrow;
            const float4 w1v = *(const float4*)(wrow + 4);
            float wv[8] = {w0v.x, w0v.y, w0v.z, w0v.w, w1v.x, w1v.y, w1v.z, w1v.w};
            const ulonglong2 hA = *(const ulonglong2*)&s_emb[e * 128 + bi];
            const ulonglong2 hB = *(const ulonglong2*)&s_emb[e * 128 + bi + 4];
            ull hp[4] = {hA.x, hA.y, hB.x, hB.y};
#pragma unroll
            for (int c8 = 0; c8 < 8; c8++) {
                ull w2 = bcast2(wv[c8]);
#pragma unroll
                for (int p = 0; p < 4; p++) acc[c8][p] = fma2(hp[p], w2, acc[c8][p]);
            }
        }
        __syncthreads();
    }

#pragma unroll
    for (int c8 = 0; c8 < 8; c8++) {
        size_t base = ((size_t)t * GG + cb + c8) * BB + bi;
#pragma unroll
        for (int p = 0; p < 4; p++)
            *(ull*)&g_xproj[base + p * 2] = acc[c8][p];
    }
}

// ---------------- kernel B: persistent recurrent loop (v5) ----------------
// 128 CTAs x 512 threads = 4 quarters x 128. Quarter q owns every 4th 32-k
// chunk of K=1024 staged h ([h0;h1]). Weights SMEM-resident as [k][16 cols];
// accumulators pack COLUMN pairs (weight ull loaded directly, h broadcast).
// Per-thread tile: 4 cols x 4 batches x 2 layers = 16 ull accumulators.
// Quarters 1-3 dump partials to smem; quarter 0 reduces; q0 does L1 gates,
// q1 does L0(t+1) gates (xproj/bias added here). One grid barrier per step.
__global__ void __launch_bounds__(512, 1) lstm_kernel(const float* __restrict__ bias1,
                                                      const float* __restrict__ Wd,
                                                      const float* __restrict__ bd,
                                                      float* __restrict__ out) {
    extern __shared__ float smem[];
    float* s_w0    = smem;                 // [512][16]  = 8192 f
    float* s_w1    = smem + 8192;          // [1024][16] = 16384 f
    float* s_stage = smem + 24576;         // 8 slots x 4096 f (quarter q: 2q, 2q+1)
    float* s_gL1   = s_stage;              // alias q0 slot0 (after drain)
    float* s_gL0   = s_stage + 4096;       // alias q0 slot1

    const int c   = blockIdx.x;
    const int tid = threadIdx.x;
    const int q   = tid >> 7;     // quarter 0..3
    const int tl  = tid & 127;
    const int cp  = tl & 3;       // 4 cols: l = 4cp..4cp+3
    const int bg  = tl >> 2;      // 0..31
    const int b0  = bg * 4;

    // ---- one-time: weights to SMEM ----
    {
        const float* w0g = g_Wq0 + (size_t)c * 8192;
        const float* w1g = g_Wq1 + (size_t)c * 16384;
        const uint32_t sw0 = (uint32_t)__cvta_generic_to_shared(s_w0);
        const uint32_t sw1 = (uint32_t)__cvta_generic_to_shared(s_w1);
        for (int i = tid; i < 2048; i += 512) cp16(sw0 + i * 16, w0g + i * 4);
        for (int i = tid; i < 4096; i += 512) cp16(sw1 + i * 16, w1g + i * 4);
        cp_commit(); cp_wait0(); __syncthreads();
    }

    // gate-stage constants / state
    float bias16[16];              // q0: [r][g]
    if (q == 0) {
#pragma unroll
        for (int r = 0; r < 4; r++)
#pragma unroll
            for (int g = 0; g < 4; g++)
                bias16[r * 4 + g] = bias1[g * 512 + c * 4 + r];
    }
    float c1s[4] = {0, 0, 0, 0};   // q0
    float c0s[4] = {0, 0, 0, 0};   // q1

    // ---- prologue: q1 computes h0(0) from xproj(0), c_prev = 0 ----
    if (q == 1) {
#pragma unroll
        for (int r = 0; r < 4; r++) {
            int gc = c * 4 + r;
            float gi = __ldcg(&g_xproj[((size_t)0 * GG + 0 * 512 + gc) * BB + tl]);
            float gj = __ldcg(&g_xproj[((size_t)0 * GG + 1 * 512 + gc) * BB + tl]);
            float go = __ldcg(&g_xproj[((size_t)0 * GG + 3 * 512 + gc) * BB + tl]);
            float cn = sigf(gi) * tanhf(gj);
            c0s[r] = cn;
            __stcg(&g_h0t[0 * HB + gc * 128 + tl], tanhf(cn) * sigf(go));
        }
    }
    grid_barrier();

    const uint32_t slotu[2] = {
        (uint32_t)__cvta_generic_to_shared(s_stage + (2 * q) * 4096),
        (uint32_t)__cvta_generic_to_shared(s_stage + (2 * q + 1) * 4096) };
    const float* slotf[2] = { s_stage + (2 * q) * 4096, s_stage + (2 * q + 1) * 4096 };

    for (int t = 0; t < TT; t++) {
        const float* h0src = g_h0t + (t & 1) * HB;          // h0(t)
        const float* h1src = g_h1t + ((t + 1) & 1) * HB;    // h1(t-1)

        // acc[ly*8 + pp*4 + bi]: ly0=L0, ly1=L1; pp: col pair (4cp+2pp, +1)
        ull acc[16];
#pragma unroll
        for (int i = 0; i < 16; i++) acc[i] = 0ull;

        // prime chunk i=0 (g = q, heavy)
        {
            const float* g = h0src + q * 4096;
#pragma unroll
            for (int p = 0; p < 8; p++) cp16(slotu[0] + (p * 128 + tl) * 16, g + (p * 128 + tl) * 4);
            cp_commit();
        }

        for (int i = 0; i < 8; i++) {
            if (i < 7) {
                const int ni = i + 1;
                const float* src = (ni < 4) ? (h0src + (q + 4 * ni) * 4096)
                                            : (h1src + (q + 4 * (ni - 4)) * 4096);
                const uint32_t sa = slotu[ni & 1];
#pragma unroll
                for (int p = 0; p < 8; p++) cp16(sa + (p * 128 + tl) * 16, src + (p * 128 + tl) * 4);
                cp_commit();
                cp_wait1();
            } else {
                cp_wait0();
            }
            asm volatile("bar.sync %0, 128;" :: "r"(1 + q) : "memory");
            const float* sh = slotf[i & 1];

            if (i < 4) {   // heavy: h0 chunk feeds both layers
                const int k0 = (q + 4 * i) * 32;
                const float* w0p = s_w0 + k0 * 16 + cp * 4;
                const float* w1p = s_w1 + k0 * 16 + cp * 4;
#pragma unroll 4
                for (int k = 0; k < 32; k++) {
                    const float4 h4 = *(const float4*)&sh[k * 128 + b0];
                    const ull hb[4] = {bcast2(h4.x), bcast2(h4.y), bcast2(h4.z), bcast2(h4.w)};
                    const ulonglong2 w0 = *(const ulonglong2*)(w0p + k * 16);
                    const ulonglong2 w1 = *(const ulonglong2*)(w1p + k * 16);
#pragma unroll
                    for (int bi = 0; bi < 4; bi++) {
                        acc[0 + bi]  = fma2(w0.x, hb[bi], acc[0 + bi]);
                        acc[4 + bi]  = fma2(w0.y, hb[bi], acc[4 + bi]);
                        acc[8 + bi]  = fma2(w1.x, hb[bi], acc[8 + bi]);
                        acc[12 + bi] = fma2(w1.y, hb[bi], acc[12 + bi]);
                    }
                }
            } else {       // light: h1 chunk feeds L1 only
                const int k0 = 512 + (q + 4 * (i - 4)) * 32;
                const float* w1p = s_w1 + k0 * 16 + cp * 4;
#pragma unroll 4
                for (int k = 0; k < 32; k++) {
                    const float4 h4 = *(const float4*)&sh[k * 128 + b0];
                    const ull hb[4] = {bcast2(h4.x), bcast2(h4.y), bcast2(h4.z), bcast2(h4.w)};
                    const ulonglong2 w1 = *(const ulonglong2*)(w1p + k * 16);
#pragma unroll
                    for (int bi = 0; bi < 4; bi++) {
                        acc[8 + bi]  = fma2(w1.x, hb[bi], acc[8 + bi]);
                        acc[12 + bi] = fma2(w1.y, hb[bi], acc[12 + bi]);
                    }
                }
            }
            asm volatile("bar.sync %0, 128;" :: "r"(1 + q) : "memory");
        }

        // ---- quarters 1-3 dump partials (ull[16][128] in own slot0) ----
        if (q != 0) {
            ull* pb = (ull*)(s_stage + (2 * q) * 4096);
#pragma unroll
            for (int i = 0; i < 16; i++) pb[i * 128 + tl] = acc[i];
        }
        __syncthreads();

        // ---- quarter 0 reduces + stages gates ----
        if (q == 0) {
#pragma unroll
            for (int j = 1; j < 4; j++) {
                const ull* pb = (const ull*)(s_stage + (2 * j) * 4096);
#pragma unroll
                for (int i = 0; i < 16; i++) acc[i] = add2(acc[i], pb[i * 128 + tl]);
            }
#pragma unroll
            for (int i = 0; i < 16; i++) {
                const int ly = i >> 3, pp = (i >> 2) & 1, bi = i & 3;
                const int l = 4 * cp + 2 * pp;
                const int b = b0 + bi;
                float* dst = ly ? s_gL1 : s_gL0;
                const float2 f = unpk2(acc[i]);
                dst[l * 132 + b]       = f.x;
                dst[(l + 1) * 132 + b] = f.y;
            }
        }
        __syncthreads();

        // ---- gates: q0 -> L1(t), q1 -> L0(t+1) ----
        if (q == 0) {
#pragma unroll
            for (int r = 0; r < 4; r++) {
                float gi = s_gL1[(0 * 4 + r) * 132 + tl] + bias16[r * 4 + 0];
                float gj = s_gL1[(1 * 4 + r) * 132 + tl] + bias16[r * 4 + 1];
                float gf = s_gL1[(2 * 4 + r) * 132 + tl] + bias16[r * 4 + 2];
                float go = s_gL1[(3 * 4 + r) * 132 + tl] + bias16[r * 4 + 3];
                float cn = c1s[r] * sigf(gf + 1.0f) + sigf(gi) * tanhf(gj);
                c1s[r] = cn;
                __stcg(&g_h1t[(t & 1) * HB + (c * 4 + r) * 128 + tl], tanhf(cn) * sigf(go));
            }
        } else if (q == 1 && t + 1 < TT) {
            const size_t tb = (size_t)(t + 1) * GG;
#pragma unroll
            for (int r = 0; r < 4; r++) {
                int gc = c * 4 + r;
                float gi = s_gL0[(0 * 4 + r) * 132 + tl] + __ldcg(&g_xproj[(tb + 0 * 512 + gc) * BB + tl]);
                float gj = s_gL0[(1 * 4 + r) * 132 + tl] + __ldcg(&g_xproj[(tb + 1 * 512 + gc) * BB + tl]);
                float gf = s_gL0[(2 * 4 + r) * 132 + tl] + __ldcg(&g_xproj[(tb + 2 * 512 + gc) * BB + tl]);
                float go = s_gL0[(3 * 4 + r) * 132 + tl] + __ldcg(&g_xproj[(tb + 3 * 512 + gc) * BB + tl]);
                float cn = c0s[r] * sigf(gf + 1.0f) + sigf(gi) * tanhf(gj);
                c0s[r] = cn;
                __stcg(&g_h0t[((t + 1) & 1) * HB + gc * 128 + tl], tanhf(cn) * sigf(go));
            }
        }
        grid_barrier();
    }

    // ---- final projection: logits = h1(T-1) . Wd + bd ----
    if (blockIdx.x == 0 && tid < 256) {
        const int b = tid & 127, oc = tid >> 7;
        const float* hf = g_h1t + ((TT - 1) & 1) * HB;
        float s = 0.0f;
#pragma unroll 8
        for (int k = 0; k < HH; k++)
            s += __ldcg(&hf[k * 128 + b]) * Wd[k * 2 + oc];
        out[b * 2 + oc] = s + bd[oc];
    }
}

// ---------------- launch ----------------
extern "C" void kernel_launch(void* const* d_in, const int* in_sizes, int n_in,
                              void* d_out, int out_size) {
    const int* xw    = (const int*)d_in[0];
    const float* emb = (const float*)d_in[1];
    const float* W0  = (const float*)d_in[2];
    const float* b0  = (const float*)d_in[3];
    const float* W1  = (const float*)d_in[4];
    const float* b1  = (const float*)d_in[5];
    const float* Wd  = (const float*)d_in[6];
    const float* bd  = (const float*)d_in[7];
    float* out       = (float*)d_out;
    (void)n_in; (void)out_size;

    const int nx   = in_sizes[0];
    const int vmax = in_sizes[1] / EE - 1;

    // weights 24576 f + staging 32768 f = 57344 f = 229376 B (<= 232448 cap)
    const int smemBytes = (24576 + 32768) * sizeof(float);
    cudaFuncSetAttribute(lstm_kernel, cudaFuncAttributeMaxDynamicSharedMemorySize, smemBytes);

    pack_kernel<<<8192, 256>>>(W0, W1);
    detect_kernel<<<(nx / 2 + 255) / 256, 256>>>(xw, nx);
    xproj_kernel<<<dim3(16, TT), 256>>>(xw, emb, W0, b0, vmax);
    lstm_kernel<<<BB, 512, smemBytes>>>(b1, Wd, bd, out);
}

// round 14
// speedup vs baseline: 3.0675x; 1.0763x over previous
#include <cuda_runtime.h>
#include <cstdint>
#include <math.h>

#define BB   128      // batch
#define TT   256      // timesteps
#define HH   512      // hidden
#define EE   300      // embed dim
#define GG   2048     // 4H
#define HB   (HH*BB)

// ---------------- device scratch (static, no allocation) ----------------
__device__ float g_xproj[(size_t)TT * GG * BB];      // [t][col][b]  256MB
__device__ float g_Wq0[(size_t)128 * 512 * 16];      // [c][k][l]  4MB
__device__ float g_Wq1[(size_t)128 * 1024 * 16];     // [c][k][l]  8MB
__device__ float g_h0t[2 * HB];                      // transposed [k][b], ping-pong
__device__ float g_h1t[2 * HB];
__device__ unsigned g_bar_count;
__device__ unsigned g_bar_gen;
__device__ int g_odd_nonzero;

// ---------------- helpers ----------------
typedef unsigned long long ull;

__device__ __forceinline__ ull bcast2(float v) {
    ull r; asm("mov.b64 %0, {%1, %1};" : "=l"(r) : "f"(v)); return r;
}
__device__ __forceinline__ ull fma2(ull a, ull b, ull c) {
    ull d; asm("fma.rn.f32x2 %0, %1, %2, %3;" : "=l"(d) : "l"(a), "l"(b), "l"(c)); return d;
}
__device__ __forceinline__ ull add2(ull a, ull b) {
    ull d; asm("add.rn.f32x2 %0, %1, %2;" : "=l"(d) : "l"(a), "l"(b)); return d;
}
__device__ __forceinline__ float2 unpk2(ull v) {
    float2 f; asm("mov.b64 {%0, %1}, %2;" : "=f"(f.x), "=f"(f.y) : "l"(v)); return f;
}
// fast gate nonlinearities (MUFU-based). Inf-safe: __fdividef(1, inf) -> 0.
__device__ __forceinline__ float sigf(float x) {
    return __fdividef(1.0f, 1.0f + __expf(-x));
}
__device__ __forceinline__ float tanhf_fast(float x) {
    x = fminf(fmaxf(x, -15.0f), 15.0f);
    float e = __expf(2.0f * x);
    return __fdividef(e - 1.0f, e + 1.0f);
}

__device__ __forceinline__ void grid_barrier() {
    __syncthreads();
    if (threadIdx.x == 0) {
        __threadfence();
        unsigned gen = *((volatile unsigned*)&g_bar_gen);
        unsigned ticket = atomicAdd(&g_bar_count, 1u);
        if (ticket == gridDim.x - 1) {
            atomicExch(&g_bar_count, 0u);
            __threadfence();
            atomicAdd(&g_bar_gen, 1u);
        } else {
            while (*((volatile unsigned*)&g_bar_gen) == gen) {}
            __threadfence();
        }
    }
    __syncthreads();
}

__device__ __forceinline__ void cp16(uint32_t saddr, const float* g) {
    asm volatile("cp.async.cg.shared.global [%0], [%1], 16;" :: "r"(saddr), "l"(g));
}
__device__ __forceinline__ void cp_commit() { asm volatile("cp.async.commit_group;"); }
__device__ __forceinline__ void cp_wait1()  { asm volatile("cp.async.wait_group 1;"); }
__device__ __forceinline__ void cp_wait0()  { asm volatile("cp.async.wait_group 0;"); }

// ---------------- kernel D: detect int32 vs int64 layout of x ----------------
__global__ void detect_kernel(const int* __restrict__ xw, int nwords) {
    int i = blockIdx.x * blockDim.x + threadIdx.x;
    int odd = 2 * i + 1;
    if (odd < nwords && xw[odd] != 0) atomicOr(&g_odd_nonzero, 1);
}

// ---------------- kernel P: pack weights [c][k][l] + zero state ----------------
// l -> gcol = (l>>2)*512 + c*4 + (l&3)   (gate = l>>2, hcol = l&3)
__global__ void pack_kernel(const float* __restrict__ W0,
                            const float* __restrict__ W1) {
    size_t i = (size_t)blockIdx.x * blockDim.x + threadIdx.x;
    const size_t N0 = (size_t)128 * 512 * 16;    // 1,048,576
    const size_t N1 = (size_t)128 * 1024 * 16;   // 2,097,152
    if (i < N0) {
        int c = (int)(i >> 13);
        int r = (int)(i & 8191);
        int k = r >> 4, l = r & 15;
        int gcol = ((l >> 2) << 9) + (c << 2) + (l & 3);
        g_Wq0[i] = W0[(size_t)(EE + k) * GG + gcol];
    }
    if (i < N1) {
        int c = (int)(i >> 14);
        int r = (int)(i & 16383);
        int k = r >> 4, l = r & 15;
        int gcol = ((l >> 2) << 9) + (c << 2) + (l & 3);
        g_Wq1[i] = W1[(size_t)k * GG + gcol];
    }
    if (i < 2 * HB) { g_h0t[i] = 0.0f; g_h1t[i] = 0.0f; }
    if (i == 0) { g_bar_count = 0; g_odd_nonzero = 0; }
}

// ---------------- kernel A: xproj[t][col][b] ----------------
__global__ void __launch_bounds__(256) xproj_kernel(const int* __restrict__ xw,
                                                    const float* __restrict__ emb,
                                                    const float* __restrict__ W0,
                                                    const float* __restrict__ bias0,
                                                    int vmax) {
    __shared__ float s_emb[88 * 128];
    __shared__ int s_row[BB];
    const int t = blockIdx.y;
    const int colbase = blockIdx.x * 128;
    const int tid = threadIdx.x;

    const int stride = g_odd_nonzero ? 1 : 2;
    if (tid < BB) {
        int idx = xw[((size_t)tid * TT + t) * stride];
        idx = idx < 0 ? 0 : (idx > vmax ? vmax : idx);
        s_row[tid] = idx;
    }

    const int cp8 = tid & 15;
    const int bg  = tid >> 4;
    const int cb  = colbase + cp8 * 8;
    const int bi  = bg * 8;

    ull acc[8][4];
#pragma unroll
    for (int c8 = 0; c8 < 8; c8++) {
        ull bv = bcast2(bias0[cb + c8]);
#pragma unroll
        for (int p = 0; p < 4; p++) acc[c8][p] = bv;
    }
    __syncthreads();

    for (int e0 = 0; e0 < EE; e0 += 88) {
        const int ec = (EE - e0 < 88) ? (EE - e0) : 88;
        const int f4cnt = ec >> 2;
        for (int fi = tid; fi < 128 * f4cnt; fi += 256) {
            int b = fi / f4cnt, j = fi % f4cnt;
            const float4 v = *(const float4*)&emb[(size_t)s_row[b] * EE + e0 + j * 4];
            s_emb[(j * 4 + 0) * 128 + b] = v.x;
            s_emb[(j * 4 + 1) * 128 + b] = v.y;
            s_emb[(j * 4 + 2) * 128 + b] = v.z;
            s_emb[(j * 4 + 3) * 128 + b] = v.w;
        }
        __syncthreads();

#pragma unroll 4
        for (int e = 0; e < ec; e++) {
            const float* wrow = W0 + (size_t)(e0 + e) * GG + cb;
            const float4 w0v = *(const float4*)wrow;
            const float4 w1v = *(const float4*)(wrow + 4);
            float wv[8] = {w0v.x, w0v.y, w0v.z, w0v.w, w1v.x, w1v.y, w1v.z, w1v.w};
            const ulonglong2 hA = *(const ulonglong2*)&s_emb[e * 128 + bi];
            const ulonglong2 hB = *(const ulonglong2*)&s_emb[e * 128 + bi + 4];
            ull hp[4] = {hA.x, hA.y, hB.x, hB.y};
#pragma unroll
            for (int c8 = 0; c8 < 8; c8++) {
                ull w2 = bcast2(wv[c8]);
#pragma unroll
                for (int p = 0; p < 4; p++) acc[c8][p] = fma2(hp[p], w2, acc[c8][p]);
            }
        }
        __syncthreads();
    }

#pragma unroll
    for (int c8 = 0; c8 < 8; c8++) {
        size_t base = ((size_t)t * GG + cb + c8) * BB + bi;
#pragma unroll
        for (int p = 0; p < 4; p++)
            *(ull*)&g_xproj[base + p * 2] = acc[c8][p];
    }
}

// ---------------- kernel B: persistent recurrent loop (v6) ----------------
// Mainloop as v5 (4-quarter k-split, SMEM weights, col-pair f32x2 packing).
// v6 tail: ALL quarters dump partials; ALL 512 threads reduce (4 positions
// each, conflict-free stride); gates split tid<256 -> L1(t), tid>=256 ->
// L0(t+1); MUFU-based sigmoid/tanh. One grid barrier per step.
__global__ void __launch_bounds__(512, 1) lstm_kernel(const float* __restrict__ bias1,
                                                      const float* __restrict__ Wd,
                                                      const float* __restrict__ bd,
                                                      float* __restrict__ out) {
    extern __shared__ float smem[];
    float* s_w0    = smem;                 // [512][16]  = 8192 f
    float* s_w1    = smem + 8192;          // [1024][16] = 16384 f
    float* s_stage = smem + 24576;         // 8 slots x 4096 f (quarter q: 2q, 2q+1)
    float* gL1buf  = s_stage + 1 * 4096;   // gate staging (odd slots: dead at tail)
    float* gL0buf  = s_stage + 3 * 4096;

    const int c   = blockIdx.x;
    const int tid = threadIdx.x;
    const int q   = tid >> 7;     // quarter 0..3
    const int tl  = tid & 127;
    const int cp  = tl & 3;       // 4 cols: l = 4cp..4cp+3
    const int bg  = tl >> 2;      // 0..31
    const int b0  = bg * 4;

    // gate-thread identity: gidx handles outputs (hc0, bq) and (hc0+2, bq)
    const int gidx = tid & 255;
    const int hc0  = gidx >> 7;       // 0 or 1
    const int bq   = gidx & 127;

    // ---- one-time: weights to SMEM ----
    {
        const float* w0g = g_Wq0 + (size_t)c * 8192;
        const float* w1g = g_Wq1 + (size_t)c * 16384;
        const uint32_t sw0 = (uint32_t)__cvta_generic_to_shared(s_w0);
        const uint32_t sw1 = (uint32_t)__cvta_generic_to_shared(s_w1);
        for (int i = tid; i < 2048; i += 512) cp16(sw0 + i * 16, w0g + i * 4);
        for (int i = tid; i < 4096; i += 512) cp16(sw1 + i * 16, w1g + i * 4);
        cp_commit(); cp_wait0(); __syncthreads();
    }

    float c1s[2] = {0, 0};   // tid < 256 : L1 cell state
    float c0s[2] = {0, 0};   // tid >= 256: L0 cell state

    // ---- prologue: L0-gate threads compute h0(0) from xproj(0), c_prev = 0 ----
    if (tid >= 256) {
#pragma unroll
        for (int r = 0; r < 2; r++) {
            int hc = hc0 + 2 * r;
            int gc = c * 4 + hc;
            float gi = __ldcg(&g_xproj[((size_t)0 * GG + 0 * 512 + gc) * BB + bq]);
            float gj = __ldcg(&g_xproj[((size_t)0 * GG + 1 * 512 + gc) * BB + bq]);
            float go = __ldcg(&g_xproj[((size_t)0 * GG + 3 * 512 + gc) * BB + bq]);
            float cn = sigf(gi) * tanhf_fast(gj);
            c0s[r] = cn;
            __stcg(&g_h0t[0 * HB + gc * 128 + bq], tanhf_fast(cn) * sigf(go));
        }
    }
    grid_barrier();

    const uint32_t slotu[2] = {
        (uint32_t)__cvta_generic_to_shared(s_stage + (2 * q) * 4096),
        (uint32_t)__cvta_generic_to_shared(s_stage + (2 * q + 1) * 4096) };
    const float* slotf[2] = { s_stage + (2 * q) * 4096, s_stage + (2 * q + 1) * 4096 };

    for (int t = 0; t < TT; t++) {
        const float* h0src = g_h0t + (t & 1) * HB;          // h0(t)
        const float* h1src = g_h1t + ((t + 1) & 1) * HB;    // h1(t-1)

        // acc[ly*8 + pp*4 + bi]: ly0=L0, ly1=L1; pp: col pair (4cp+2pp, +1)
        ull acc[16];
#pragma unroll
        for (int i = 0; i < 16; i++) acc[i] = 0ull;

        // prime chunk i=0 (g = q, heavy)
        {
            const float* g = h0src + q * 4096;
#pragma unroll
            for (int p = 0; p < 8; p++) cp16(slotu[0] + (p * 128 + tl) * 16, g + (p * 128 + tl) * 4);
            cp_commit();
        }

        for (int i = 0; i < 8; i++) {
            if (i < 7) {
                const int ni = i + 1;
                const float* src = (ni < 4) ? (h0src + (q + 4 * ni) * 4096)
                                            : (h1src + (q + 4 * (ni - 4)) * 4096);
                const uint32_t sa = slotu[ni & 1];
#pragma unroll
                for (int p = 0; p < 8; p++) cp16(sa + (p * 128 + tl) * 16, src + (p * 128 + tl) * 4);
                cp_commit();
                cp_wait1();
            } else {
                cp_wait0();
            }
            asm volatile("bar.sync %0, 128;" :: "r"(1 + q) : "memory");
            const float* sh = slotf[i & 1];

            if (i < 4) {   // heavy: h0 chunk feeds both layers
                const int k0 = (q + 4 * i) * 32;
                const float* w0p = s_w0 + k0 * 16 + cp * 4;
                const float* w1p = s_w1 + k0 * 16 + cp * 4;
#pragma unroll 4
                for (int k = 0; k < 32; k++) {
                    const float4 h4 = *(const float4*)&sh[k * 128 + b0];
                    const ull hb[4] = {bcast2(h4.x), bcast2(h4.y), bcast2(h4.z), bcast2(h4.w)};
                    const ulonglong2 w0 = *(const ulonglong2*)(w0p + k * 16);
                    const ulonglong2 w1 = *(const ulonglong2*)(w1p + k * 16);
#pragma unroll
                    for (int bi = 0; bi < 4; bi++) {
                        acc[0 + bi]  = fma2(w0.x, hb[bi], acc[0 + bi]);
                        acc[4 + bi]  = fma2(w0.y, hb[bi], acc[4 + bi]);
                        acc[8 + bi]  = fma2(w1.x, hb[bi], acc[8 + bi]);
                        acc[12 + bi] = fma2(w1.y, hb[bi], acc[12 + bi]);
                    }
                }
            } else {       // light: h1 chunk feeds L1 only
                const int k0 = 512 + (q + 4 * (i - 4)) * 32;
                const float* w1p = s_w1 + k0 * 16 + cp * 4;
#pragma unroll 4
                for (int k = 0; k < 32; k++) {
                    const float4 h4 = *(const float4*)&sh[k * 128 + b0];
                    const ull hb[4] = {bcast2(h4.x), bcast2(h4.y), bcast2(h4.z), bcast2(h4.w)};
                    const ulonglong2 w1 = *(const ulonglong2*)(w1p + k * 16);
#pragma unroll
                    for (int bi = 0; bi < 4; bi++) {
                        acc[8 + bi]  = fma2(w1.x, hb[bi], acc[8 + bi]);
                        acc[12 + bi] = fma2(w1.y, hb[bi], acc[12 + bi]);
                    }
                }
            }
            asm volatile("bar.sync %0, 128;" :: "r"(1 + q) : "memory");
        }

        // ---- xproj prefetch for L0-gate threads (overlaps dump+reduce) ----
        const int tn = (t + 1 < TT) ? (t + 1) : t;
        float xp[2][4];
        if (tid >= 256) {
            const size_t tb = (size_t)tn * GG;
#pragma unroll
            for (int g = 0; g < 4; g++) {
                xp[0][g] = __ldcg(&g_xproj[(tb + g * 512 + c * 4 + hc0) * BB + bq]);
                xp[1][g] = __ldcg(&g_xproj[(tb + g * 512 + c * 4 + hc0 + 2) * BB + bq]);
            }
        }

        // ---- all quarters dump partials to their even slot ----
        {
            ull* pb = (ull*)(s_stage + (2 * q) * 4096);
#pragma unroll
            for (int i = 0; i < 16; i++) pb[i * 128 + tl] = acc[i];
        }
        __syncthreads();

        // ---- parallel reduce: each thread 4 positions (stride 512) ----
        {
            const ull* P0 = (const ull*)(s_stage + 0 * 4096);
            const ull* P1 = (const ull*)(s_stage + 2 * 4096);
            const ull* P2 = (const ull*)(s_stage + 4 * 4096);
            const ull* P3 = (const ull*)(s_stage + 6 * 4096);
#pragma unroll
            for (int j = 0; j < 4; j++) {
                const int pos = tid + j * 512;
                const ull v = add2(add2(P0[pos], P1[pos]), add2(P2[pos], P3[pos]));
                const int i = pos >> 7, t2 = pos & 127;
                const int ly = i >> 3, pp = (i >> 2) & 1, bi = i & 3;
                const int l = 4 * (t2 & 3) + 2 * pp;
                const int b = 4 * (t2 >> 2) + bi;
                float* dst = ly ? gL1buf : gL0buf;
                const float2 f = unpk2(v);
                dst[l * 132 + b]       = f.x;
                dst[(l + 1) * 132 + b] = f.y;
            }
        }
        __syncthreads();

        // ---- gates: tid<256 -> L1(t); tid>=256 -> L0(t+1) ----
        if (tid < 256) {
#pragma unroll
            for (int r = 0; r < 2; r++) {
                int hc = hc0 + 2 * r;
                int gc = c * 4 + hc;
                float gi = gL1buf[(0 * 4 + hc) * 132 + bq] + __ldg(&bias1[0 * 512 + gc]);
                float gj = gL1buf[(1 * 4 + hc) * 132 + bq] + __ldg(&bias1[1 * 512 + gc]);
                float gf = gL1buf[(2 * 4 + hc) * 132 + bq] + __ldg(&bias1[2 * 512 + gc]);
                float go = gL1buf[(3 * 4 + hc) * 132 + bq] + __ldg(&bias1[3 * 512 + gc]);
                float cn = c1s[r] * sigf(gf + 1.0f) + sigf(gi) * tanhf_fast(gj);
                c1s[r] = cn;
                __stcg(&g_h1t[(t & 1) * HB + gc * 128 + bq], tanhf_fast(cn) * sigf(go));
            }
        } else if (t + 1 < TT) {
#pragma unroll
            for (int r = 0; r < 2; r++) {
                int hc = hc0 + 2 * r;
                int gc = c * 4 + hc;
                float gi = gL0buf[(0 * 4 + hc) * 132 + bq] + xp[r][0];
                float gj = gL0buf[(1 * 4 + hc) * 132 + bq] + xp[r][1];
                float gf = gL0buf[(2 * 4 + hc) * 132 + bq] + xp[r][2];
                float go = gL0buf[(3 * 4 + hc) * 132 + bq] + xp[r][3];
                float cn = c0s[r] * sigf(gf + 1.0f) + sigf(gi) * tanhf_fast(gj);
                c0s[r] = cn;
                __stcg(&g_h0t[((t + 1) & 1) * HB + gc * 128 + bq], tanhf_fast(cn) * sigf(go));
            }
        }
        grid_barrier();
    }

    // ---- final projection: logits = h1(T-1) . Wd + bd ----
    if (blockIdx.x == 0 && tid < 256) {
        const int b = tid & 127, oc = tid >> 7;
        const float* hf = g_h1t + ((TT - 1) & 1) * HB;
        float s = 0.0f;
#pragma unroll 8
        for (int k = 0; k < HH; k++)
            s += __ldcg(&hf[k * 128 + b]) * Wd[k * 2 + oc];
        out[b * 2 + oc] = s + bd[oc];
    }
}

// ---------------- launch ----------------
extern "C" void kernel_launch(void* const* d_in, const int* in_sizes, int n_in,
                              void* d_out, int out_size) {
    const int* xw    = (const int*)d_in[0];
    const float* emb = (const float*)d_in[1];
    const float* W0  = (const float*)d_in[2];
    const float* b0  = (const float*)d_in[3];
    const float* W1  = (const float*)d_in[4];
    const float* b1  = (const float*)d_in[5];
    const float* Wd  = (const float*)d_in[6];
    const float* bd  = (const float*)d_in[7];
    float* out       = (float*)d_out;
    (void)n_in; (void)out_size;

    const int nx   = in_sizes[0];
    const int vmax = in_sizes[1] / EE - 1;

    // weights 24576 f + staging 32768 f = 57344 f = 229376 B (<= cap)
    const int smemBytes = (24576 + 32768) * sizeof(float);
    cudaFuncSetAttribute(lstm_kernel, cudaFuncAttributeMaxDynamicSharedMemorySize, smemBytes);

    pack_kernel<<<8192, 256>>>(W0, W1);
    detect_kernel<<<(nx / 2 + 255) / 256, 256>>>(xw, nx);
    xproj_kernel<<<dim3(16, TT), 256>>>(xw, emb, W0, b0, vmax);
    lstm_kernel<<<BB, 512, smemBytes>>>(b1, Wd, bd, out);
}

// round 15
// speedup vs baseline: 3.1481x; 1.0263x over previous
#include <cuda_runtime.h>
#include <cstdint>
#include <math.h>

#define BB   128      // batch
#define TT   256      // timesteps
#define HH   512      // hidden
#define EE   300      // embed dim
#define GG   2048     // 4H
#define HB   (HH*BB)

// ---------------- device scratch (static, no allocation) ----------------
__device__ float g_xproj[(size_t)TT * GG * BB];      // [t][col][b]  256MB
__device__ float g_Wq0[(size_t)128 * 512 * 16];      // [c][k][l]  4MB
__device__ float g_Wq1[(size_t)128 * 1024 * 16];     // [c][k][l]  8MB
__device__ float g_h0t[2 * HB];                      // transposed [k][b], ping-pong
__device__ float g_h1t[2 * HB];
__device__ unsigned g_epoch_ctr;                     // monotonic barrier counter
__device__ int g_odd_nonzero;

// ---------------- helpers ----------------
typedef unsigned long long ull;

__device__ __forceinline__ ull bcast2(float v) {
    ull r; asm("mov.b64 %0, {%1, %1};" : "=l"(r) : "f"(v)); return r;
}
__device__ __forceinline__ ull fma2(ull a, ull b, ull c) {
    ull d; asm("fma.rn.f32x2 %0, %1, %2, %3;" : "=l"(d) : "l"(a), "l"(b), "l"(c)); return d;
}
__device__ __forceinline__ ull add2(ull a, ull b) {
    ull d; asm("add.rn.f32x2 %0, %1, %2;" : "=l"(d) : "l"(a), "l"(b)); return d;
}
__device__ __forceinline__ float2 unpk2(ull v) {
    float2 f; asm("mov.b64 {%0, %1}, %2;" : "=f"(f.x), "=f"(f.y) : "l"(v)); return f;
}
// fast gate nonlinearities (MUFU-based). Inf-safe: __fdividef(1, inf) -> 0.
__device__ __forceinline__ float sigf(float x) {
    return __fdividef(1.0f, 1.0f + __expf(-x));
}
__device__ __forceinline__ float tanhf_fast(float x) {
    x = fminf(fmaxf(x, -15.0f), 15.0f);
    float e = __expf(2.0f * x);
    return __fdividef(e - 1.0f, e + 1.0f);
}

// monotonic epoch grid barrier: REDG arrival (release), acquire polling, no reset.
__device__ __forceinline__ void grid_barrier_to(unsigned target) {
    __syncthreads();
    if (threadIdx.x == 0) {
        asm volatile("red.release.gpu.global.add.u32 [%0], 1;"
                     :: "l"(&g_epoch_ctr) : "memory");
        unsigned v;
        do {
            asm volatile("ld.acquire.gpu.global.u32 %0, [%1];"
                         : "=r"(v) : "l"(&g_epoch_ctr) : "memory");
        } while (v < target);
    }
    __syncthreads();
}

__device__ __forceinline__ void cp16(uint32_t saddr, const float* g) {
    asm volatile("cp.async.cg.shared.global [%0], [%1], 16;" :: "r"(saddr), "l"(g));
}
__device__ __forceinline__ void cp_commit() { asm volatile("cp.async.commit_group;"); }
__device__ __forceinline__ void cp_wait1()  { asm volatile("cp.async.wait_group 1;"); }
__device__ __forceinline__ void cp_wait0()  { asm volatile("cp.async.wait_group 0;"); }

// ---------------- kernel D: detect int32 vs int64 layout of x ----------------
__global__ void detect_kernel(const int* __restrict__ xw, int nwords) {
    int i = blockIdx.x * blockDim.x + threadIdx.x;
    int odd = 2 * i + 1;
    if (odd < nwords && xw[odd] != 0) atomicOr(&g_odd_nonzero, 1);
}

// ---------------- kernel P: pack weights [c][k][l] + zero state ----------------
// l -> gcol = (l>>2)*512 + c*4 + (l&3)   (gate = l>>2, hcol = l&3)
__global__ void pack_kernel(const float* __restrict__ W0,
                            const float* __restrict__ W1) {
    size_t i = (size_t)blockIdx.x * blockDim.x + threadIdx.x;
    const size_t N0 = (size_t)128 * 512 * 16;    // 1,048,576
    const size_t N1 = (size_t)128 * 1024 * 16;   // 2,097,152
    if (i < N0) {
        int c = (int)(i >> 13);
        int r = (int)(i & 8191);
        int k = r >> 4, l = r & 15;
        int gcol = ((l >> 2) << 9) + (c << 2) + (l & 3);
        g_Wq0[i] = W0[(size_t)(EE + k) * GG + gcol];
    }
    if (i < N1) {
        int c = (int)(i >> 14);
        int r = (int)(i & 16383);
        int k = r >> 4, l = r & 15;
        int gcol = ((l >> 2) << 9) + (c << 2) + (l & 3);
        g_Wq1[i] = W1[(size_t)k * GG + gcol];
    }
    if (i < 2 * HB) { g_h0t[i] = 0.0f; g_h1t[i] = 0.0f; }
    if (i == 0) { g_epoch_ctr = 0; g_odd_nonzero = 0; }
}

// ---------------- kernel A: xproj[t][col][b] ----------------
__global__ void __launch_bounds__(256) xproj_kernel(const int* __restrict__ xw,
                                                    const float* __restrict__ emb,
                                                    const float* __restrict__ W0,
                                                    const float* __restrict__ bias0,
                                                    int vmax) {
    __shared__ float s_emb[88 * 128];
    __shared__ int s_row[BB];
    const int t = blockIdx.y;
    const int colbase = blockIdx.x * 128;
    const int tid = threadIdx.x;

    const int stride = g_odd_nonzero ? 1 : 2;
    if (tid < BB) {
        int idx = xw[((size_t)tid * TT + t) * stride];
        idx = idx < 0 ? 0 : (idx > vmax ? vmax : idx);
        s_row[tid] = idx;
    }

    const int cp8 = tid & 15;
    const int bg  = tid >> 4;
    const int cb  = colbase + cp8 * 8;
    const int bi  = bg * 8;

    ull acc[8][4];
#pragma unroll
    for (int c8 = 0; c8 < 8; c8++) {
        ull bv = bcast2(bias0[cb + c8]);
#pragma unroll
        for (int p = 0; p < 4; p++) acc[c8][p] = bv;
    }
    __syncthreads();

    for (int e0 = 0; e0 < EE; e0 += 88) {
        const int ec = (EE - e0 < 88) ? (EE - e0) : 88;
        const int f4cnt = ec >> 2;
        for (int fi = tid; fi < 128 * f4cnt; fi += 256) {
            int b = fi / f4cnt, j = fi % f4cnt;
            const float4 v = *(const float4*)&emb[(size_t)s_row[b] * EE + e0 + j * 4];
            s_emb[(j * 4 + 0) * 128 + b] = v.x;
            s_emb[(j * 4 + 1) * 128 + b] = v.y;
            s_emb[(j * 4 + 2) * 128 + b] = v.z;
            s_emb[(j * 4 + 3) * 128 + b] = v.w;
        }
        __syncthreads();

#pragma unroll 4
        for (int e = 0; e < ec; e++) {
            const float* wrow = W0 + (size_t)(e0 + e) * GG + cb;
            const float4 w0v = *(const float4*)wrow;
            const float4 w1v = *(const float4*)(wrow + 4);
            float wv[8] = {w0v.x, w0v.y, w0v.z, w0v.w, w1v.x, w1v.y, w1v.z, w1v.w};
            const ulonglong2 hA = *(const ulonglong2*)&s_emb[e * 128 + bi];
            const ulonglong2 hB = *(const ulonglong2*)&s_emb[e * 128 + bi + 4];
            ull hp[4] = {hA.x, hA.y, hB.x, hB.y};
#pragma unroll
            for (int c8 = 0; c8 < 8; c8++) {
                ull w2 = bcast2(wv[c8]);
#pragma unroll
                for (int p = 0; p < 4; p++) acc[c8][p] = fma2(hp[p], w2, acc[c8][p]);
            }
        }
        __syncthreads();
    }

#pragma unroll
    for (int c8 = 0; c8 < 8; c8++) {
        size_t base = ((size_t)t * GG + cb + c8) * BB + bi;
#pragma unroll
        for (int p = 0; p < 4; p++)
            *(ull*)&g_xproj[base + p * 2] = acc[c8][p];
    }
}

// ---------------- kernel B: persistent recurrent loop (v7) ----------------
// Mainloop as v5/v6 (4-quarter k-split, SMEM weights, col-pair f32x2 packing,
// all-thread reduce, split gates). v7: monotonic REDG epoch grid barrier
// (release/acquire, no contended RMW-with-return, no threadfence, no reset);
// bias1 addends hoisted to registers.
__global__ void __launch_bounds__(512, 1) lstm_kernel(const float* __restrict__ bias1,
                                                      const float* __restrict__ Wd,
                                                      const float* __restrict__ bd,
                                                      float* __restrict__ out) {
    extern __shared__ float smem[];
    float* s_w0    = smem;                 // [512][16]  = 8192 f
    float* s_w1    = smem + 8192;          // [1024][16] = 16384 f
    float* s_stage = smem + 24576;         // 8 slots x 4096 f (quarter q: 2q, 2q+1)
    float* gL1buf  = s_stage + 1 * 4096;   // gate staging (odd slots: dead at tail)
    float* gL0buf  = s_stage + 3 * 4096;

    const int c   = blockIdx.x;
    const int tid = threadIdx.x;
    const int q   = tid >> 7;     // quarter 0..3
    const int tl  = tid & 127;
    const int cp  = tl & 3;       // 4 cols: l = 4cp..4cp+3
    const int bg  = tl >> 2;      // 0..31
    const int b0  = bg * 4;

    // gate-thread identity: gidx handles outputs (hc0, bq) and (hc0+2, bq)
    const int gidx = tid & 255;
    const int hc0  = gidx >> 7;       // 0 or 1
    const int bq   = gidx & 127;

    unsigned bar_target = 0;

    // ---- one-time: weights to SMEM ----
    {
        const float* w0g = g_Wq0 + (size_t)c * 8192;
        const float* w1g = g_Wq1 + (size_t)c * 16384;
        const uint32_t sw0 = (uint32_t)__cvta_generic_to_shared(s_w0);
        const uint32_t sw1 = (uint32_t)__cvta_generic_to_shared(s_w1);
        for (int i = tid; i < 2048; i += 512) cp16(sw0 + i * 16, w0g + i * 4);
        for (int i = tid; i < 4096; i += 512) cp16(sw1 + i * 16, w1g + i * 4);
        cp_commit(); cp_wait0(); __syncthreads();
    }

    float c1s[2] = {0, 0};   // tid < 256 : L1 cell state
    float c0s[2] = {0, 0};   // tid >= 256: L0 cell state

    // hoisted L1 bias addends (tid < 256 only meaningful)
    float b1r[2][4];
    if (tid < 256) {
#pragma unroll
        for (int r = 0; r < 2; r++) {
            int gc = c * 4 + hc0 + 2 * r;
#pragma unroll
            for (int g = 0; g < 4; g++) b1r[r][g] = bias1[g * 512 + gc];
        }
    }

    // ---- prologue: L0-gate threads compute h0(0) from xproj(0), c_prev = 0 ----
    if (tid >= 256) {
#pragma unroll
        for (int r = 0; r < 2; r++) {
            int hc = hc0 + 2 * r;
            int gc = c * 4 + hc;
            float gi = __ldcg(&g_xproj[((size_t)0 * GG + 0 * 512 + gc) * BB + bq]);
            float gj = __ldcg(&g_xproj[((size_t)0 * GG + 1 * 512 + gc) * BB + bq]);
            float go = __ldcg(&g_xproj[((size_t)0 * GG + 3 * 512 + gc) * BB + bq]);
            float cn = sigf(gi) * tanhf_fast(gj);
            c0s[r] = cn;
            __stcg(&g_h0t[0 * HB + gc * 128 + bq], tanhf_fast(cn) * sigf(go));
        }
    }
    bar_target += 128; grid_barrier_to(bar_target);

    const uint32_t slotu[2] = {
        (uint32_t)__cvta_generic_to_shared(s_stage + (2 * q) * 4096),
        (uint32_t)__cvta_generic_to_shared(s_stage + (2 * q + 1) * 4096) };
    const float* slotf[2] = { s_stage + (2 * q) * 4096, s_stage + (2 * q + 1) * 4096 };

    for (int t = 0; t < TT; t++) {
        const float* h0src = g_h0t + (t & 1) * HB;          // h0(t)
        const float* h1src = g_h1t + ((t + 1) & 1) * HB;    // h1(t-1)

        // acc[ly*8 + pp*4 + bi]: ly0=L0, ly1=L1; pp: col pair (4cp+2pp, +1)
        ull acc[16];
#pragma unroll
        for (int i = 0; i < 16; i++) acc[i] = 0ull;

        // prime chunk i=0 (g = q, heavy)
        {
            const float* g = h0src + q * 4096;
#pragma unroll
            for (int p = 0; p < 8; p++) cp16(slotu[0] + (p * 128 + tl) * 16, g + (p * 128 + tl) * 4);
            cp_commit();
        }

        for (int i = 0; i < 8; i++) {
            if (i < 7) {
                const int ni = i + 1;
                const float* src = (ni < 4) ? (h0src + (q + 4 * ni) * 4096)
                                            : (h1src + (q + 4 * (ni - 4)) * 4096);
                const uint32_t sa = slotu[ni & 1];
#pragma unroll
                for (int p = 0; p < 8; p++) cp16(sa + (p * 128 + tl) * 16, src + (p * 128 + tl) * 4);
                cp_commit();
                cp_wait1();
            } else {
                cp_wait0();
            }
            asm volatile("bar.sync %0, 128;" :: "r"(1 + q) : "memory");
            const float* sh = slotf[i & 1];

            if (i < 4) {   // heavy: h0 chunk feeds both layers
                const int k0 = (q + 4 * i) * 32;
                const float* w0p = s_w0 + k0 * 16 + cp * 4;
                const float* w1p = s_w1 + k0 * 16 + cp * 4;
#pragma unroll 4
                for (int k = 0; k < 32; k++) {
                    const float4 h4 = *(const float4*)&sh[k * 128 + b0];
                    const ull hb[4] = {bcast2(h4.x), bcast2(h4.y), bcast2(h4.z), bcast2(h4.w)};
                    const ulonglong2 w0 = *(const ulonglong2*)(w0p + k * 16);
                    const ulonglong2 w1 = *(const ulonglong2*)(w1p + k * 16);
#pragma unroll
                    for (int bi = 0; bi < 4; bi++) {
                        acc[0 + bi]  = fma2(w0.x, hb[bi], acc[0 + bi]);
                        acc[4 + bi]  = fma2(w0.y, hb[bi], acc[4 + bi]);
                        acc[8 + bi]  = fma2(w1.x, hb[bi], acc[8 + bi]);
                        acc[12 + bi] = fma2(w1.y, hb[bi], acc[12 + bi]);
                    }
                }
            } else {       // light: h1 chunk feeds L1 only
                const int k0 = 512 + (q + 4 * (i - 4)) * 32;
                const float* w1p = s_w1 + k0 * 16 + cp * 4;
#pragma unroll 4
                for (int k = 0; k < 32; k++) {
                    const float4 h4 = *(const float4*)&sh[k * 128 + b0];
                    const ull hb[4] = {bcast2(h4.x), bcast2(h4.y), bcast2(h4.z), bcast2(h4.w)};
                    const ulonglong2 w1 = *(const ulonglong2*)(w1p + k * 16);
#pragma unroll
                    for (int bi = 0; bi < 4; bi++) {
                        acc[8 + bi]  = fma2(w1.x, hb[bi], acc[8 + bi]);
                        acc[12 + bi] = fma2(w1.y, hb[bi], acc[12 + bi]);
                    }
                }
            }
            asm volatile("bar.sync %0, 128;" :: "r"(1 + q) : "memory");
        }

        // ---- xproj prefetch for L0-gate threads (overlaps dump+reduce) ----
        const int tn = (t + 1 < TT) ? (t + 1) : t;
        float xp[2][4];
        if (tid >= 256) {
            const size_t tb = (size_t)tn * GG;
#pragma unroll
            for (int g = 0; g < 4; g++) {
                xp[0][g] = __ldcg(&g_xproj[(tb + g * 512 + c * 4 + hc0) * BB + bq]);
                xp[1][g] = __ldcg(&g_xproj[(tb + g * 512 + c * 4 + hc0 + 2) * BB + bq]);
            }
        }

        // ---- all quarters dump partials to their even slot ----
        {
            ull* pb = (ull*)(s_stage + (2 * q) * 4096);
#pragma unroll
            for (int i = 0; i < 16; i++) pb[i * 128 + tl] = acc[i];
        }
        __syncthreads();

        // ---- parallel reduce: each thread 4 positions (stride 512) ----
        {
            const ull* P0 = (const ull*)(s_stage + 0 * 4096);
            const ull* P1 = (const ull*)(s_stage + 2 * 4096);
            const ull* P2 = (const ull*)(s_stage + 4 * 4096);
            const ull* P3 = (const ull*)(s_stage + 6 * 4096);
#pragma unroll
            for (int j = 0; j < 4; j++) {
                const int pos = tid + j * 512;
                const ull v = add2(add2(P0[pos], P1[pos]), add2(P2[pos], P3[pos]));
                const int i = pos >> 7, t2 = pos & 127;
                const int ly = i >> 3, pp = (i >> 2) & 1, bi = i & 3;
                const int l = 4 * (t2 & 3) + 2 * pp;
                const int b = 4 * (t2 >> 2) + bi;
                float* dst = ly ? gL1buf : gL0buf;
                const float2 f = unpk2(v);
                dst[l * 132 + b]       = f.x;
                dst[(l + 1) * 132 + b] = f.y;
            }
        }
        __syncthreads();

        // ---- gates: tid<256 -> L1(t); tid>=256 -> L0(t+1) ----
        if (tid < 256) {
#pragma unroll
            for (int r = 0; r < 2; r++) {
                int hc = hc0 + 2 * r;
                int gc = c * 4 + hc;
                float gi = gL1buf[(0 * 4 + hc) * 132 + bq] + b1r[r][0];
                float gj = gL1buf[(1 * 4 + hc) * 132 + bq] + b1r[r][1];
                float gf = gL1buf[(2 * 4 + hc) * 132 + bq] + b1r[r][2];
                float go = gL1buf[(3 * 4 + hc) * 132 + bq] + b1r[r][3];
                float cn = c1s[r] * sigf(gf + 1.0f) + sigf(gi) * tanhf_fast(gj);
                c1s[r] = cn;
                __stcg(&g_h1t[(t & 1) * HB + gc * 128 + bq], tanhf_fast(cn) * sigf(go));
            }
        } else if (t + 1 < TT) {
#pragma unroll
            for (int r = 0; r < 2; r++) {
                int hc = hc0 + 2 * r;
                int gc = c * 4 + hc;
                float gi = gL0buf[(0 * 4 + hc) * 132 + bq] + xp[r][0];
                float gj = gL0buf[(1 * 4 + hc) * 132 + bq] + xp[r][1];
                float gf = gL0buf[(2 * 4 + hc) * 132 + bq] + xp[r][2];
                float go = gL0buf[(3 * 4 + hc) * 132 + bq] + xp[r][3];
                float cn = c0s[r] * sigf(gf + 1.0f) + sigf(gi) * tanhf_fast(gj);
                c0s[r] = cn;
                __stcg(&g_h0t[((t + 1) & 1) * HB + gc * 128 + bq], tanhf_fast(cn) * sigf(go));
            }
        }
        bar_target += 128; grid_barrier_to(bar_target);
    }

    // ---- final projection: logits = h1(T-1) . Wd + bd ----
    if (blockIdx.x == 0 && tid < 256) {
        const int b = tid & 127, oc = tid >> 7;
        const float* hf = g_h1t + ((TT - 1) & 1) * HB;
        float s = 0.0f;
#pragma unroll 8
        for (int k = 0; k < HH; k++)
            s += __ldcg(&hf[k * 128 + b]) * Wd[k * 2 + oc];
        out[b * 2 + oc] = s + bd[oc];
    }
}

// ---------------- launch ----------------
extern "C" void kernel_launch(void* const* d_in, const int* in_sizes, int n_in,
                              void* d_out, int out_size) {
    const int* xw    = (const int*)d_in[0];
    const float* emb = (const float*)d_in[1];
    const float* W0  = (const float*)d_in[2];
    const float* b0  = (const float*)d_in[3];
    const float* W1  = (const float*)d_in[4];
    const float* b1  = (const float*)d_in[5];
    const float* Wd  = (const float*)d_in[6];
    const float* bd  = (const float*)d_in[7];
    float* out       = (float*)d_out;
    (void)n_in; (void)out_size;

    const int nx   = in_sizes[0];
    const int vmax = in_sizes[1] / EE - 1;

    // weights 24576 f + staging 32768 f = 57344 f = 229376 B (<= cap)
    const int smemBytes = (24576 + 32768) * sizeof(float);
    cudaFuncSetAttribute(lstm_kernel, cudaFuncAttributeMaxDynamicSharedMemorySize, smemBytes);

    pack_kernel<<<8192, 256>>>(W0, W1);
    detect_kernel<<<(nx / 2 + 255) / 256, 256>>>(xw, nx);
    xproj_kernel<<<dim3(16, TT), 256>>>(xw, emb, W0, b0, vmax);
    lstm_kernel<<<BB, 512, smemBytes>>>(b1, Wd, bd, out);
}